// round 15
// baseline (speedup 1.0000x reference)
#include <cuda_runtime.h>
#include <cuda_bf16.h>
#include <cstdint>
#include <cstddef>

#define NN 4096
#define TT 24
#define FF 16
#define HH 128
#define GG 384
#define NHD 4
#define DOD 32
#define SEMD 64
#define PHD 32

// ---------------- scratch (static device globals; no runtime allocation) ----
__device__ float g_support[NN * HH];
__device__ float g_supP[NN * HH];
__device__ float g_supN[NN * HH];
__device__ float g_residP[NN * HH];
__device__ float g_residN[NN * HH];
__device__ float g_selfE[NN * HH];
__device__ float g_f1P[NHD * NN];
__device__ float g_f2P[NHD * NN];
__device__ float g_f1N[NHD * NN];
__device__ float g_f2N[NHD * NN];
__device__ float g_gatP[NN * HH];
__device__ float g_gatN[NN * HH];
__device__ float g_posE[NN * HH];
__device__ float g_negE[NN * HH];
__device__ float g_fused[NN * HH];
__device__ float g_colsum[HH];
// bf16 fragment-ordered Whh: hi (register-staged per warp), lo (streamed)
__device__ __align__(16) uint32_t g_Bhi[8 * 8 * 6 * 32 * 2];   // 24576 words
__device__ __align__(16) uint32_t g_Blo[8 * 8 * 2 * 32 * 8];   // 32768 words
// bf16 fragment-ordered Wih (k=16 -> one k-chunk)
__device__ __align__(16) uint32_t g_WihHi[8 * 6 * 32 * 2];
__device__ __align__(16) uint32_t g_WihLo[8 * 2 * 32 * 8];

__device__ __forceinline__ float warpsum(float v) {
#pragma unroll
    for (int o = 16; o >= 1; o >>= 1) v += __shfl_down_sync(0xffffffffu, v, o);
    return v;
}
__device__ __forceinline__ float warpsum_bfly(float v) {
#pragma unroll
    for (int o = 16; o >= 1; o >>= 1) v += __shfl_xor_sync(0xffffffffu, v, o);
    return v;
}
__device__ __forceinline__ float sigmoid_fast(float x) {
    return __fdividef(1.f, 1.f + __expf(-x));
}
__device__ __forceinline__ float tanh_fast(float x) {
    float e = __expf(-2.f * x);
    return __fdividef(2.f, 1.f + e) - 1.f;
}
__device__ __forceinline__ void mma_bf16(float d[4], const uint32_t a[4],
                                         uint32_t b0, uint32_t b1) {
    asm volatile("mma.sync.aligned.m16n8k16.row.col.f32.bf16.bf16.f32 "
                 "{%0,%1,%2,%3}, {%4,%5,%6,%7}, {%8,%9}, {%0,%1,%2,%3};"
                 : "+f"(d[0]), "+f"(d[1]), "+f"(d[2]), "+f"(d[3])
                 : "r"(a[0]), "r"(a[1]), "r"(a[2]), "r"(a[3]), "r"(b0), "r"(b1));
}

// ---------------- kernel 0: combined prep (Whh + Wih + colsum zero) ---------
__global__ void k_prep_all(const float* __restrict__ Whh,
                           const float* __restrict__ Wih) {
    int blk = blockIdx.x;
    if (blk < 48) {
        int idx = blk * 256 + threadIdx.x;           // 12288 = 8*8*6*32
        int lane = idx & 31; int r = idx >> 5;
        int nt = r % 6; r /= 6;
        int w8 = r & 7; int kt = r >> 3;
        int g = nt >> 1, s = nt & 1;
        int n = g * 128 + w8 * 16 + s * 8 + (lane >> 2);
        int kb = kt * 16 + (lane & 3) * 2;
        float w0 = Whh[n * 128 + kb],     w1 = Whh[n * 128 + kb + 1];
        float w2 = Whh[n * 128 + kb + 8], w3 = Whh[n * 128 + kb + 9];
        __nv_bfloat16 h0 = __float2bfloat16(w0), h1 = __float2bfloat16(w1);
        __nv_bfloat16 h2 = __float2bfloat16(w2), h3 = __float2bfloat16(w3);
        {
            __nv_bfloat162 v; v.x = h0; v.y = h1;
            g_Bhi[idx * 2 + 0] = *(uint32_t*)&v;
            v.x = h2; v.y = h3;
            g_Bhi[idx * 2 + 1] = *(uint32_t*)&v;
        }
        __nv_bfloat162 l01, l23;
        l01.x = __float2bfloat16(w0 - __bfloat162float(h0));
        l01.y = __float2bfloat16(w1 - __bfloat162float(h1));
        l23.x = __float2bfloat16(w2 - __bfloat162float(h2));
        l23.y = __float2bfloat16(w3 - __bfloat162float(h3));
        uint32_t* lo = &g_Blo[(((kt * 8 + w8) * 2 + s) * 32 + lane) * 8 + g * 2];
        lo[0] = *(uint32_t*)&l01;
        lo[1] = *(uint32_t*)&l23;
    } else {
        int idx = (blk - 48) * 256 + threadIdx.x;    // 1536 = 8*6*32
        int lane = idx & 31; int r = idx >> 5;
        int nt = r % 6; int w8 = r / 6;
        int g = nt >> 1, s = nt & 1;
        int n = g * 128 + w8 * 16 + s * 8 + (lane >> 2);
        int kb = (lane & 3) * 2;
        float w0 = Wih[n * FF + kb],     w1 = Wih[n * FF + kb + 1];
        float w2 = Wih[n * FF + kb + 8], w3 = Wih[n * FF + kb + 9];
        __nv_bfloat16 h0 = __float2bfloat16(w0), h1 = __float2bfloat16(w1);
        __nv_bfloat16 h2 = __float2bfloat16(w2), h3 = __float2bfloat16(w3);
        {
            __nv_bfloat162 v; v.x = h0; v.y = h1;
            g_WihHi[idx * 2 + 0] = *(uint32_t*)&v;
            v.x = h2; v.y = h3;
            g_WihHi[idx * 2 + 1] = *(uint32_t*)&v;
        }
        __nv_bfloat162 l01, l23;
        l01.x = __float2bfloat16(w0 - __bfloat162float(h0));
        l01.y = __float2bfloat16(w1 - __bfloat162float(h1));
        l23.x = __float2bfloat16(w2 - __bfloat162float(h2));
        l23.y = __float2bfloat16(w3 - __bfloat162float(h3));
        uint32_t* lo = &g_WihLo[((w8 * 2 + s) * 32 + lane) * 8 + g * 2];
        lo[0] = *(uint32_t*)&l01;
        lo[1] = *(uint32_t*)&l23;
        if (blk == 48 && threadIdx.x < HH) g_colsum[threadIdx.x] = 0.f;
    }
}

// ---------------- kernel 2: fused GRU, 256 thr, B-hi in registers -----------
#define HBUF 2176

__global__ void __launch_bounds__(256, 1) k_gru(const float* __restrict__ feat,
                                                const float* __restrict__ bih,
                                                const float* __restrict__ bhh) {
    __shared__ __align__(16) uint32_t hbase[4 * HBUF];   // 34.8 KB
    int tid = threadIdx.x;
    int w = tid >> 5, lane = tid & 31;
    int qr = lane >> 2, qc = lane & 3;
    int node0 = blockIdx.x * 32;

    const uint2* Bhi2g = (const uint2*)g_Bhi;
    uint2 bhr[8][3][2];
#pragma unroll
    for (int kt = 0; kt < 8; kt++)
#pragma unroll
        for (int g = 0; g < 3; g++)
#pragma unroll
            for (int s = 0; s < 2; s++)
                bhr[kt][g][s] = __ldg(&Bhi2g[((kt * 8 + w) * 6 + g * 2 + s) * 32 + lane]);

    for (int i = tid; i < 4 * HBUF; i += 256) hbase[i] = 0u;

    float bRr[2][2], bRz[2][2], biN[2][2], bhN[2][2];
#pragma unroll
    for (int s = 0; s < 2; s++)
#pragma unroll
        for (int jj = 0; jj < 2; jj++) {
            int c = w * 16 + s * 8 + 2 * qc + jj;
            bRr[s][jj] = __ldg(&bih[c]) + __ldg(&bhh[c]);
            bRz[s][jj] = __ldg(&bih[128 + c]) + __ldg(&bhh[128 + c]);
            biN[s][jj] = __ldg(&bih[256 + c]);
            bhN[s][jj] = __ldg(&bhh[256 + c]);
        }
    __syncthreads();

    const uint2* WihHi2 = (const uint2*)g_WihHi;
    int cur = 0;

    for (int t = 0; t < TT; t++) {
        uint32_t* h_hi_w = hbase + cur * (2 * HBUF);
        uint32_t* h_lo_w = h_hi_w + HBUF;
        uint32_t* n_hi_w = hbase + (cur ^ 1) * (2 * HBUF);
        uint32_t* n_lo_w = n_hi_w + HBUF;

        uint32_t xh[2][4], xl[2][4];
#pragma unroll
        for (int m = 0; m < 2; m++) {
            const float* base = feat + (size_t)(node0 + m * 16) * (TT * FF) + t * FF;
            float2 v[4];
            v[0] = __ldg((const float2*)(base + (size_t)qr * (TT * FF) + 2 * qc));
            v[1] = __ldg((const float2*)(base + (size_t)(qr + 8) * (TT * FF) + 2 * qc));
            v[2] = __ldg((const float2*)(base + (size_t)qr * (TT * FF) + 2 * qc + 8));
            v[3] = __ldg((const float2*)(base + (size_t)(qr + 8) * (TT * FF) + 2 * qc + 8));
#pragma unroll
            for (int j = 0; j < 4; j++) {
                __nv_bfloat162 hv; hv.x = __float2bfloat16(v[j].x); hv.y = __float2bfloat16(v[j].y);
                xh[m][j] = *(uint32_t*)&hv;
                __nv_bfloat162 lv;
                lv.x = __float2bfloat16(v[j].x - __bfloat162float(hv.x));
                lv.y = __float2bfloat16(v[j].y - __bfloat162float(hv.y));
                xl[m][j] = *(uint32_t*)&lv;
            }
        }

        float d[2][3][2][4];
        float dx[2][2][4];
#pragma unroll
        for (int m = 0; m < 2; m++) {
#pragma unroll
            for (int g = 0; g < 3; g++)
#pragma unroll
                for (int s = 0; s < 2; s++)
#pragma unroll
                    for (int j = 0; j < 4; j++) d[m][g][s][j] = 0.f;
#pragma unroll
            for (int s = 0; s < 2; s++)
#pragma unroll
                for (int j = 0; j < 4; j++) dx[m][s][j] = 0.f;
        }

        // ---- x @ Wih^T (k=16) ----
#pragma unroll
        for (int s = 0; s < 2; s++) {
            const uint32_t* p = &g_WihLo[((w * 2 + s) * 32 + lane) * 8];
            uint4 wlA = __ldg((const uint4*)p);
            uint2 wlB = __ldg((const uint2*)(p + 4));
            uint32_t wlw[6] = {wlA.x, wlA.y, wlA.z, wlA.w, wlB.x, wlB.y};
#pragma unroll
            for (int g = 0; g < 3; g++) {
                uint2 bh = __ldg(&WihHi2[(w * 6 + g * 2 + s) * 32 + lane]);
#pragma unroll
                for (int m = 0; m < 2; m++) {
                    float* D = (g == 2) ? dx[m][s] : d[m][g][s];
                    mma_bf16(D, xh[m], bh.x, bh.y);
                    mma_bf16(D, xl[m], bh.x, bh.y);
                    mma_bf16(D, xh[m], wlw[g * 2], wlw[g * 2 + 1]);
                }
            }
        }

        // ---- h @ Whh^T (bf16, B-hi from registers, lo streamed) ----
        if (t) {
#pragma unroll
            for (int kt = 0; kt < 8; kt++) {
                uint32_t ah[2][4], al[2][4];
#pragma unroll
                for (int m = 0; m < 2; m++) {
                    int r0 = (m * 16 + qr) * 68 + kt * 8 + qc;
                    ah[m][0] = h_hi_w[r0];
                    ah[m][1] = h_hi_w[r0 + 8 * 68];
                    ah[m][2] = h_hi_w[r0 + 4];
                    ah[m][3] = h_hi_w[r0 + 8 * 68 + 4];
                    al[m][0] = h_lo_w[r0];
                    al[m][1] = h_lo_w[r0 + 8 * 68];
                    al[m][2] = h_lo_w[r0 + 4];
                    al[m][3] = h_lo_w[r0 + 8 * 68 + 4];
                }
#pragma unroll
                for (int s = 0; s < 2; s++) {
                    const uint32_t* p = &g_Blo[(((kt * 8 + w) * 2 + s) * 32 + lane) * 8];
                    uint4 lA = __ldg((const uint4*)p);
                    uint2 lB = __ldg((const uint2*)(p + 4));
                    uint32_t lw[6] = {lA.x, lA.y, lA.z, lA.w, lB.x, lB.y};
#pragma unroll
                    for (int g = 0; g < 3; g++) {
                        uint2 bh = bhr[kt][g][s];
#pragma unroll
                        for (int m = 0; m < 2; m++) {
                            mma_bf16(d[m][g][s], ah[m], bh.x, bh.y);
                            mma_bf16(d[m][g][s], al[m], bh.x, bh.y);
                            mma_bf16(d[m][g][s], ah[m], lw[g * 2], lw[g * 2 + 1]);
                        }
                    }
                }
            }
        }

        // ---- gate math: read h[cur], write h[nxt], single barrier ----
#pragma unroll
        for (int m = 0; m < 2; m++)
#pragma unroll
            for (int s = 0; s < 2; s++)
#pragma unroll
                for (int rg = 0; rg < 2; rg++) {
                    int row = m * 16 + qr + rg * 8;
                    int wi = row * 68 + w * 8 + s * 4 + qc;
                    float2 hhf = __bfloat1622float2(*(__nv_bfloat162*)&h_hi_w[wi]);
                    float2 hlf = __bfloat1622float2(*(__nv_bfloat162*)&h_lo_w[wi]);
                    float hn[2];
#pragma unroll
                    for (int jj = 0; jj < 2; jj++) {
                        float hold = jj ? (hhf.y + hlf.y) : (hhf.x + hlf.x);
                        int di = rg * 2 + jj;
                        float rr = sigmoid_fast(d[m][0][s][di] + bRr[s][jj]);
                        float zz = sigmoid_fast(d[m][1][s][di] + bRz[s][jj]);
                        float nv = tanh_fast(dx[m][s][di] + biN[s][jj] +
                                             rr * (d[m][2][s][di] + bhN[s][jj]));
                        hn[jj] = (1.f - zz) * nv + zz * hold;
                    }
                    __nv_bfloat162 hv; hv.x = __float2bfloat16(hn[0]); hv.y = __float2bfloat16(hn[1]);
                    __nv_bfloat162 lv;
                    lv.x = __float2bfloat16(hn[0] - __bfloat162float(hv.x));
                    lv.y = __float2bfloat16(hn[1] - __bfloat162float(hv.y));
                    n_hi_w[wi] = *(uint32_t*)&hv;
                    n_lo_w[wi] = *(uint32_t*)&lv;
                }
        __syncthreads();
        cur ^= 1;
    }

    const __nv_bfloat16* h_hi = (const __nv_bfloat16*)(hbase + cur * (2 * HBUF));
    const __nv_bfloat16* h_lo = h_hi + 2 * HBUF;
    for (int i = tid; i < 32 * HH; i += 256) {
        int row = i >> 7, col = i & 127;
        g_support[(size_t)(node0 + row) * HH + col] =
            __bfloat162float(h_hi[row * 136 + col]) +
            __bfloat162float(h_lo[row * 136 + col]);
    }
}

// ---------------- kernel 3: bf16 GEMM C = A @ B (+b1+b2) [+f1/f2 epilogue] --
struct GemmJob {
    const float* A; const float* B; const float* b1; const float* b2; float* C;
    const float* u; const float* v; float* f1; float* f2;
};
struct GemmJobs { GemmJob j[5]; };

#define GEMM_SMEM (4 * 128 * 136 * 2)   // 139264 B

__global__ void __launch_bounds__(256) k_gemm(GemmJobs jobs) {
    GemmJob job = jobs.j[blockIdx.y];
    extern __shared__ char smc[];
    uint16_t* As_hi = (uint16_t*)smc;
    uint16_t* As_lo = As_hi + 128 * 136;
    uint16_t* Bs_hi = As_lo + 128 * 136;
    uint16_t* Bs_lo = Bs_hi + 128 * 136;
    int tid = threadIdx.x;
    int node0 = blockIdx.x * 128;

    for (int idx = tid; idx < 128 * 128; idx += 256) {
        int r = idx >> 7, c = idx & 127;
        float a = job.A[(size_t)(node0 + r) * HH + c];
        __nv_bfloat16 ah = __float2bfloat16(a);
        As_hi[r * 136 + c] = __bfloat16_as_ushort(ah);
        As_lo[r * 136 + c] =
            __bfloat16_as_ushort(__float2bfloat16(a - __bfloat162float(ah)));
        float b = job.B[idx];
        __nv_bfloat16 bh = __float2bfloat16(b);
        Bs_hi[c * 136 + r] = __bfloat16_as_ushort(bh);
        Bs_lo[c * 136 + r] =
            __bfloat16_as_ushort(__float2bfloat16(b - __bfloat162float(bh)));
    }
    __syncthreads();

    int w = tid >> 5, lane = tid & 31;
    int qr = lane >> 2, qc = lane & 3;
    int r0 = w * 16;
    const uint32_t* Aw_hi = (const uint32_t*)As_hi;
    const uint32_t* Aw_lo = (const uint32_t*)As_lo;
    const uint32_t* Bw_hi = (const uint32_t*)Bs_hi;
    const uint32_t* Bw_lo = (const uint32_t*)Bs_lo;

    float acc[16][4];
#pragma unroll
    for (int ct = 0; ct < 16; ct++)
#pragma unroll
        for (int j = 0; j < 4; j++) acc[ct][j] = 0.f;

#pragma unroll 1
    for (int kt = 0; kt < 8; kt++) {
        int kc = kt * 8 + qc;
        uint32_t ah[4], al[4];
        ah[0] = Aw_hi[(r0 + qr) * 68 + kc];
        ah[1] = Aw_hi[(r0 + qr + 8) * 68 + kc];
        ah[2] = Aw_hi[(r0 + qr) * 68 + kc + 4];
        ah[3] = Aw_hi[(r0 + qr + 8) * 68 + kc + 4];
        al[0] = Aw_lo[(r0 + qr) * 68 + kc];
        al[1] = Aw_lo[(r0 + qr + 8) * 68 + kc];
        al[2] = Aw_lo[(r0 + qr) * 68 + kc + 4];
        al[3] = Aw_lo[(r0 + qr + 8) * 68 + kc + 4];
#pragma unroll
        for (int cg = 0; cg < 4; cg++) {
            uint32_t bh0[4], bh1[4], bl0[4], bl1[4];
#pragma unroll
            for (int j = 0; j < 4; j++) {
                int n0 = (cg * 4 + j) * 8;
                bh0[j] = Bw_hi[(n0 + qr) * 68 + kc];
                bh1[j] = Bw_hi[(n0 + qr) * 68 + kc + 4];
                bl0[j] = Bw_lo[(n0 + qr) * 68 + kc];
                bl1[j] = Bw_lo[(n0 + qr) * 68 + kc + 4];
            }
#pragma unroll
            for (int j = 0; j < 4; j++)
                mma_bf16(acc[cg * 4 + j], ah, bh0[j], bh1[j]);
#pragma unroll
            for (int j = 0; j < 4; j++)
                mma_bf16(acc[cg * 4 + j], al, bh0[j], bh1[j]);
#pragma unroll
            for (int j = 0; j < 4; j++)
                mma_bf16(acc[cg * 4 + j], ah, bl0[j], bl1[j]);
        }
    }

#pragma unroll
    for (int ct = 0; ct < 16; ct++) {
        int c0 = ct * 8 + 2 * qc;
        float b0 = 0.f, b1v = 0.f;
        if (job.b1) { b0 += __ldg(&job.b1[c0]); b1v += __ldg(&job.b1[c0 + 1]); }
        if (job.b2) { b0 += __ldg(&job.b2[c0]); b1v += __ldg(&job.b2[c0 + 1]); }
        acc[ct][0] += b0; acc[ct][1] += b1v;
        acc[ct][2] += b0; acc[ct][3] += b1v;
        int r = node0 + r0 + qr;
        *(float2*)&job.C[(size_t)r * HH + c0] = make_float2(acc[ct][0], acc[ct][1]);
        *(float2*)&job.C[(size_t)(r + 8) * HH + c0] = make_float2(acc[ct][2], acc[ct][3]);
    }

    // ---- fused f1/f2 epilogue (attention logits per head) ----
    if (job.u) {
        float f1p[2][4], f2p[2][4];
#pragma unroll
        for (int rh = 0; rh < 2; rh++)
#pragma unroll
            for (int h = 0; h < 4; h++) { f1p[rh][h] = 0.f; f2p[rh][h] = 0.f; }
#pragma unroll
        for (int ct = 0; ct < 16; ct++) {
            int h = ct >> 2;
            int c0 = ct * 8 + 2 * qc;
            float u0 = __ldg(&job.u[c0]),     u1 = __ldg(&job.u[c0 + 1]);
            float v0 = __ldg(&job.v[c0]),     v1 = __ldg(&job.v[c0 + 1]);
            f1p[0][h] += acc[ct][0] * u0 + acc[ct][1] * u1;
            f2p[0][h] += acc[ct][0] * v0 + acc[ct][1] * v1;
            f1p[1][h] += acc[ct][2] * u0 + acc[ct][3] * u1;
            f2p[1][h] += acc[ct][2] * v0 + acc[ct][3] * v1;
        }
#pragma unroll
        for (int rh = 0; rh < 2; rh++)
#pragma unroll
            for (int h = 0; h < 4; h++) {
                f1p[rh][h] += __shfl_xor_sync(0xffffffffu, f1p[rh][h], 1);
                f1p[rh][h] += __shfl_xor_sync(0xffffffffu, f1p[rh][h], 2);
                f2p[rh][h] += __shfl_xor_sync(0xffffffffu, f2p[rh][h], 1);
                f2p[rh][h] += __shfl_xor_sync(0xffffffffu, f2p[rh][h], 2);
            }
        if (qc == 0) {
#pragma unroll
            for (int rh = 0; rh < 2; rh++) {
                int r = node0 + r0 + qr + rh * 8;
#pragma unroll
                for (int h = 0; h < 4; h++) {
                    job.f1[h * NN + r] = f1p[rh][h];
                    job.f2[h * NN + r] = f2p[rh][h];
                }
            }
        }
    }
}

// ---------------- kernel 5: GAT masked-attention aggregation -----------------
__global__ void __launch_bounds__(128) k_gat(const float* __restrict__ adjP,
                                             const float* __restrict__ adjN) {
    __shared__ int s_cnt;
    __shared__ int s_list[640];
    __shared__ float s_a[640];
    const float* adj; const float* sup; const float* f1; const float* f2;
    const float* resid; float* outp;
    if (blockIdx.y == 0) { adj = adjP; sup = g_supP; f1 = g_f1P; f2 = g_f2P; resid = g_residP; outp = g_gatP; }
    else                 { adj = adjN; sup = g_supN; f1 = g_f1N; f2 = g_f2N; resid = g_residN; outp = g_gatN; }
    int i = blockIdx.x, tid = threadIdx.x;
    int h = tid >> 5;
    if (tid == 0) s_cnt = 0;
    __syncthreads();
    // scan with all-zero fast path (1 OR-reduce + 1 branch per 16 B)
    const uint4* row = (const uint4*)(adj + (size_t)i * NN);
#pragma unroll 2
    for (int j4 = tid; j4 < NN / 4; j4 += 128) {
        uint4 a = __ldg(&row[j4]);
        if (a.x | a.y | a.z | a.w) {
            float ax = __uint_as_float(a.x), ay = __uint_as_float(a.y);
            float az = __uint_as_float(a.z), aw = __uint_as_float(a.w);
            if (ax != 0.f) { int p = atomicAdd(&s_cnt, 1); s_list[p] = j4 * 4 + 0; s_a[p] = ax; }
            if (ay != 0.f) { int p = atomicAdd(&s_cnt, 1); s_list[p] = j4 * 4 + 1; s_a[p] = ay; }
            if (az != 0.f) { int p = atomicAdd(&s_cnt, 1); s_list[p] = j4 * 4 + 2; s_a[p] = az; }
            if (aw != 0.f) { int p = atomicAdd(&s_cnt, 1); s_list[p] = j4 * 4 + 3; s_a[p] = aw; }
        }
    }
    __syncthreads();
    int cnt = s_cnt;
    float f2i = f2[h * NN + i];
    float num = 0.f, den = 0.f;

    int t = 0;
    for (; t + 4 <= cnt; t += 4) {
        int j0 = s_list[t],     j1 = s_list[t + 1];
        int j2 = s_list[t + 2], j3 = s_list[t + 3];
        float a0 = s_a[t],     a1 = s_a[t + 1];
        float a2 = s_a[t + 2], a3 = s_a[t + 3];
        float w0 = __ldg(&f1[h * NN + j0]) + f2i;
        float w1 = __ldg(&f1[h * NN + j1]) + f2i;
        float w2 = __ldg(&f1[h * NN + j2]) + f2i;
        float w3 = __ldg(&f1[h * NN + j3]) + f2i;
        float s0 = __ldg(&sup[(size_t)j0 * HH + tid]);
        float s1 = __ldg(&sup[(size_t)j1 * HH + tid]);
        float s2 = __ldg(&sup[(size_t)j2 * HH + tid]);
        float s3 = __ldg(&sup[(size_t)j3 * HH + tid]);
        w0 = ((w0 > 0.f) ? w0 : 0.2f * w0) * a0;
        w1 = ((w1 > 0.f) ? w1 : 0.2f * w1) * a1;
        w2 = ((w2 > 0.f) ? w2 : 0.2f * w2) * a2;
        w3 = ((w3 > 0.f) ? w3 : 0.2f * w3) * a3;
        den += (w0 + w1) + (w2 + w3);
        num += w0 * s0 + w1 * s1 + w2 * s2 + w3 * s3;
    }
    for (; t < cnt; t++) {
        int j = s_list[t];
        float wv = __ldg(&f1[h * NN + j]) + f2i;
        wv = ((wv > 0.f) ? wv : 0.2f * wv) * s_a[t];
        den += wv;
        num += wv * __ldg(&sup[(size_t)j * HH + tid]);
    }
    float d = (den == 0.f) ? 1.f : den;
    outp[(size_t)i * HH + tid] = num / d + resid[(size_t)i * HH + tid];
}

// ---------------- kernel 7: semantic attention, warp-per-node ----------------
__global__ void __launch_bounds__(256) k_sem(const float* __restrict__ W1,
                                             const float* __restrict__ b1,
                                             const float* __restrict__ W2) {
    __shared__ float W1s[128 * 65];
    __shared__ float W2s[SEMD], b1s[SEMD];
    __shared__ float semb[8][3][128];
    int tid = threadIdx.x;
    for (int i = tid; i < 128 * 64; i += 256) {
        int k = i >> 6, s = i & 63;
        W1s[k * 65 + s] = W1[i];
    }
    if (tid < SEMD) { W2s[tid] = W2[tid]; b1s[tid] = b1[tid]; }
    __syncthreads();

    int w = tid >> 5, lane = tid & 31;
    float csum[4] = {0.f, 0.f, 0.f, 0.f};
    int nbase = (blockIdx.x * 8 + w) * 8;

    for (int i = 0; i < 8; i++) {
        int n = nbase + i;
        float4 ev[3];
        ev[0] = *(const float4*)&g_selfE[(size_t)n * HH + lane * 4];
        ev[1] = *(const float4*)&g_posE[(size_t)n * HH + lane * 4];
        ev[2] = *(const float4*)&g_negE[(size_t)n * HH + lane * 4];
        __syncwarp();
        *(float4*)&semb[w][0][lane * 4] = ev[0];
        *(float4*)&semb[w][1][lane * 4] = ev[1];
        *(float4*)&semb[w][2][lane * 4] = ev[2];
        __syncwarp();

        float acc[3][2];
#pragma unroll
        for (int e = 0; e < 3; e++) { acc[e][0] = b1s[lane]; acc[e][1] = b1s[lane + 32]; }
#pragma unroll 4
        for (int k = 0; k < HH; k++) {
            float w1a = W1s[k * 65 + lane];
            float w1b = W1s[k * 65 + lane + 32];
            float x0 = semb[w][0][k], x1 = semb[w][1][k], x2 = semb[w][2][k];
            acc[0][0] += x0 * w1a; acc[0][1] += x0 * w1b;
            acc[1][0] += x1 * w1a; acc[1][1] += x1 * w1b;
            acc[2][0] += x2 * w1a; acc[2][1] += x2 * w1b;
        }
        float wv[3];
#pragma unroll
        for (int e = 0; e < 3; e++) {
            float tsum = tanh_fast(acc[e][0]) * W2s[lane] +
                         tanh_fast(acc[e][1]) * W2s[lane + 32];
            wv[e] = warpsum_bfly(tsum);
        }
        float m = fmaxf(wv[0], fmaxf(wv[1], wv[2]));
        float e0 = __expf(wv[0] - m), e1 = __expf(wv[1] - m), e2 = __expf(wv[2] - m);
        float inv = __fdividef(1.f, e0 + e1 + e2);
        float be0 = e0 * inv, be1 = e1 * inv, be2 = e2 * inv;
        float4 f;
        f.x = be0 * ev[0].x + be1 * ev[1].x + be2 * ev[2].x;
        f.y = be0 * ev[0].y + be1 * ev[1].y + be2 * ev[2].y;
        f.z = be0 * ev[0].z + be1 * ev[1].z + be2 * ev[2].z;
        f.w = be0 * ev[0].w + be1 * ev[1].w + be2 * ev[2].w;
        *(float4*)&g_fused[(size_t)n * HH + lane * 4] = f;
        csum[0] += f.x; csum[1] += f.y; csum[2] += f.z; csum[3] += f.w;
    }
    atomicAdd(&g_colsum[lane * 4 + 0], csum[0]);
    atomicAdd(&g_colsum[lane * 4 + 1], csum[1]);
    atomicAdd(&g_colsum[lane * 4 + 2], csum[2]);
    atomicAdd(&g_colsum[lane * 4 + 3], csum[3]);
}

// ---------------- kernel 8: pairnorm + predictor -----------------------------
__global__ void __launch_bounds__(256) k_pred(const float* __restrict__ W1,
                                              const float* __restrict__ b1,
                                              const float* __restrict__ W2,
                                              const float* __restrict__ b2,
                                              float* __restrict__ out) {
    __shared__ float W1s[HH * PHD];
    __shared__ float xns[8][HH];
    int tid = threadIdx.x;
    for (int i = tid; i < HH * PHD; i += 256) W1s[i] = W1[i];
    int w = tid >> 5, lane = tid & 31;
    int n = blockIdx.x * 8 + w;
    float xv[4]; float ss = 0.f;
    const float invN = 1.f / (float)NN;
#pragma unroll
    for (int j = 0; j < 4; j++) {
        int d = lane + j * 32;
        float x = g_fused[(size_t)n * HH + d] - g_colsum[d] * invN;
        xv[j] = x; ss += x * x;
    }
    ss = warpsum(ss);
    ss = __shfl_sync(0xffffffffu, ss, 0);
    float rinv = rsqrtf(1e-6f + ss);
#pragma unroll
    for (int j = 0; j < 4; j++) xns[w][lane + j * 32] = xv[j] * rinv;
    __syncthreads();

    float acc = b1[lane];
#pragma unroll 4
    for (int k = 0; k < HH; k++) acc += xns[w][k] * W1s[k * PHD + lane];
    float hgt = acc > 0.f ? acc : 0.f;
    float o = warpsum(hgt * W2[lane]);
    if (lane == 0) out[n] = sigmoid_fast(o + b2[0]);
}

// ---------------- launch -----------------------------------------------------
extern "C" void kernel_launch(void* const* d_in, const int* in_sizes, int n_in,
                              void* d_out, int out_size) {
    const float* features = (const float*)d_in[0];
    const float* pos_adj  = (const float*)d_in[1];
    const float* neg_adj  = (const float*)d_in[2];
    const float* gru_Wih  = (const float*)d_in[3];
    const float* gru_Whh  = (const float*)d_in[4];
    const float* gru_bih  = (const float*)d_in[5];
    const float* gru_bhh  = (const float*)d_in[6];
    const float* pos_W    = (const float*)d_in[7];
    const float* pos_u    = (const float*)d_in[8];
    const float* pos_v    = (const float*)d_in[9];
    const float* pos_b    = (const float*)d_in[10];
    const float* pos_pW   = (const float*)d_in[11];
    const float* pos_pb   = (const float*)d_in[12];
    const float* neg_W    = (const float*)d_in[13];
    const float* neg_u    = (const float*)d_in[14];
    const float* neg_v    = (const float*)d_in[15];
    const float* neg_b    = (const float*)d_in[16];
    const float* neg_pW   = (const float*)d_in[17];
    const float* neg_pb   = (const float*)d_in[18];
    const float* self_W   = (const float*)d_in[19];
    const float* self_b   = (const float*)d_in[20];
    const float* mpos_W   = (const float*)d_in[21];
    const float* mpos_b   = (const float*)d_in[22];
    const float* mneg_W   = (const float*)d_in[23];
    const float* mneg_b   = (const float*)d_in[24];
    const float* sem_W1   = (const float*)d_in[25];
    const float* sem_b1   = (const float*)d_in[26];
    const float* sem_W2   = (const float*)d_in[27];
    const float* pred_W1  = (const float*)d_in[28];
    const float* pred_b1  = (const float*)d_in[29];
    const float* pred_W2  = (const float*)d_in[30];
    const float* pred_b2  = (const float*)d_in[31];
    float* out = (float*)d_out;

    static bool attr_done = false;
    if (!attr_done) {
        cudaFuncSetAttribute(k_gemm, cudaFuncAttributeMaxDynamicSharedMemorySize, GEMM_SMEM);
        attr_done = true;
    }

    float *p_support, *p_gatP, *p_gatN, *p_supP, *p_supN;
    float *p_residP, *p_residN, *p_selfE, *p_posE, *p_negE;
    float *p_f1P, *p_f2P, *p_f1N, *p_f2N;
    cudaGetSymbolAddress((void**)&p_support, g_support);
    cudaGetSymbolAddress((void**)&p_supP, g_supP);
    cudaGetSymbolAddress((void**)&p_supN, g_supN);
    cudaGetSymbolAddress((void**)&p_residP, g_residP);
    cudaGetSymbolAddress((void**)&p_residN, g_residN);
    cudaGetSymbolAddress((void**)&p_selfE, g_selfE);
    cudaGetSymbolAddress((void**)&p_gatP, g_gatP);
    cudaGetSymbolAddress((void**)&p_gatN, g_gatN);
    cudaGetSymbolAddress((void**)&p_posE, g_posE);
    cudaGetSymbolAddress((void**)&p_negE, g_negE);
    cudaGetSymbolAddress((void**)&p_f1P, g_f1P);
    cudaGetSymbolAddress((void**)&p_f2P, g_f2P);
    cudaGetSymbolAddress((void**)&p_f1N, g_f1N);
    cudaGetSymbolAddress((void**)&p_f2N, g_f2N);

    k_prep_all<<<54, 256>>>(gru_Whh, gru_Wih);                      // 1
    k_gru<<<NN / 32, 256>>>(features, gru_bih, gru_bhh);            // 2
    {
        GemmJobs jb;
        jb.j[0] = { p_support, pos_W,  nullptr, nullptr, p_supP, pos_u, pos_v, p_f1P, p_f2P };
        jb.j[1] = { p_support, neg_W,  nullptr, nullptr, p_supN, neg_u, neg_v, p_f1N, p_f2N };
        jb.j[2] = { p_support, pos_pW, pos_b,   pos_pb,  p_residP, nullptr, nullptr, nullptr, nullptr };
        jb.j[3] = { p_support, neg_pW, neg_b,   neg_pb,  p_residN, nullptr, nullptr, nullptr, nullptr };
        jb.j[4] = { p_support, self_W, self_b,  nullptr, p_selfE, nullptr, nullptr, nullptr, nullptr };
        dim3 grid(NN / 128, 5);
        k_gemm<<<grid, 256, GEMM_SMEM>>>(jb);                       // 3
    }
    {
        dim3 grid(NN, 2);
        k_gat<<<grid, 128>>>(pos_adj, neg_adj);                     // 4
    }
    {
        GemmJobs jb;
        jb.j[0] = { p_gatP, mpos_W, mpos_b, nullptr, p_posE, nullptr, nullptr, nullptr, nullptr };
        jb.j[1] = { p_gatN, mneg_W, mneg_b, nullptr, p_negE, nullptr, nullptr, nullptr, nullptr };
        jb.j[2] = jb.j[0]; jb.j[3] = jb.j[0]; jb.j[4] = jb.j[0];
        dim3 grid(NN / 128, 2);
        k_gemm<<<grid, 256, GEMM_SMEM>>>(jb);                       // 5
    }
    k_sem<<<NN / 64, 256>>>(sem_W1, sem_b1, sem_W2);                // 6
    k_pred<<<NN / 8, 256>>>(pred_W1, pred_b1, pred_W2, pred_b2, out); // 7
}

// round 16
// speedup vs baseline: 1.0305x; 1.0305x over previous
#include <cuda_runtime.h>
#include <cuda_bf16.h>
#include <cstdint>
#include <cstddef>

#define NN 4096
#define TT 24
#define FF 16
#define HH 128
#define GG 384
#define NHD 4
#define DOD 32
#define SEMD 64
#define PHD 32

// ---------------- scratch (static device globals; no runtime allocation) ----
__device__ float g_support[NN * HH];
__device__ float g_supP[NN * HH];
__device__ float g_supN[NN * HH];
__device__ float g_residP[NN * HH];
__device__ float g_residN[NN * HH];
__device__ float g_selfE[NN * HH];
__device__ float g_f1P[NHD * NN];
__device__ float g_f2P[NHD * NN];
__device__ float g_f1N[NHD * NN];
__device__ float g_f2N[NHD * NN];
__device__ float g_gatP[NN * HH];
__device__ float g_gatN[NN * HH];
__device__ float g_posE[NN * HH];
__device__ float g_negE[NN * HH];
__device__ float g_fused[NN * HH];
__device__ float g_colsum[HH];
// bf16 fragment-ordered Whh: hi (register-staged per warp), lo (streamed)
__device__ __align__(16) uint32_t g_Bhi[8 * 8 * 6 * 32 * 2];   // 24576 words
__device__ __align__(16) uint32_t g_Blo[8 * 8 * 2 * 32 * 8];   // 32768 words
// bf16 fragment-ordered Wih (k=16 -> one k-chunk)
__device__ __align__(16) uint32_t g_WihHi[8 * 6 * 32 * 2];
__device__ __align__(16) uint32_t g_WihLo[8 * 2 * 32 * 8];

__device__ __forceinline__ float warpsum(float v) {
#pragma unroll
    for (int o = 16; o >= 1; o >>= 1) v += __shfl_down_sync(0xffffffffu, v, o);
    return v;
}
__device__ __forceinline__ float warpsum_bfly(float v) {
#pragma unroll
    for (int o = 16; o >= 1; o >>= 1) v += __shfl_xor_sync(0xffffffffu, v, o);
    return v;
}
__device__ __forceinline__ float sigmoid_fast(float x) {
    return __fdividef(1.f, 1.f + __expf(-x));
}
__device__ __forceinline__ float tanh_fast(float x) {
    float e = __expf(-2.f * x);
    return __fdividef(2.f, 1.f + e) - 1.f;
}
__device__ __forceinline__ void mma_bf16(float d[4], const uint32_t a[4],
                                         uint32_t b0, uint32_t b1) {
    asm volatile("mma.sync.aligned.m16n8k16.row.col.f32.bf16.bf16.f32 "
                 "{%0,%1,%2,%3}, {%4,%5,%6,%7}, {%8,%9}, {%0,%1,%2,%3};"
                 : "+f"(d[0]), "+f"(d[1]), "+f"(d[2]), "+f"(d[3])
                 : "r"(a[0]), "r"(a[1]), "r"(a[2]), "r"(a[3]), "r"(b0), "r"(b1));
}

// ---------------- kernel 0: combined prep (Whh + Wih + colsum zero) ---------
__global__ void k_prep_all(const float* __restrict__ Whh,
                           const float* __restrict__ Wih) {
    int blk = blockIdx.x;
    if (blk < 48) {
        int idx = blk * 256 + threadIdx.x;           // 12288 = 8*8*6*32
        int lane = idx & 31; int r = idx >> 5;
        int nt = r % 6; r /= 6;
        int w8 = r & 7; int kt = r >> 3;
        int g = nt >> 1, s = nt & 1;
        int n = g * 128 + w8 * 16 + s * 8 + (lane >> 2);
        int kb = kt * 16 + (lane & 3) * 2;
        float w0 = Whh[n * 128 + kb],     w1 = Whh[n * 128 + kb + 1];
        float w2 = Whh[n * 128 + kb + 8], w3 = Whh[n * 128 + kb + 9];
        __nv_bfloat16 h0 = __float2bfloat16(w0), h1 = __float2bfloat16(w1);
        __nv_bfloat16 h2 = __float2bfloat16(w2), h3 = __float2bfloat16(w3);
        {
            __nv_bfloat162 v; v.x = h0; v.y = h1;
            g_Bhi[idx * 2 + 0] = *(uint32_t*)&v;
            v.x = h2; v.y = h3;
            g_Bhi[idx * 2 + 1] = *(uint32_t*)&v;
        }
        __nv_bfloat162 l01, l23;
        l01.x = __float2bfloat16(w0 - __bfloat162float(h0));
        l01.y = __float2bfloat16(w1 - __bfloat162float(h1));
        l23.x = __float2bfloat16(w2 - __bfloat162float(h2));
        l23.y = __float2bfloat16(w3 - __bfloat162float(h3));
        uint32_t* lo = &g_Blo[(((kt * 8 + w8) * 2 + s) * 32 + lane) * 8 + g * 2];
        lo[0] = *(uint32_t*)&l01;
        lo[1] = *(uint32_t*)&l23;
    } else {
        int idx = (blk - 48) * 256 + threadIdx.x;    // 1536 = 8*6*32
        int lane = idx & 31; int r = idx >> 5;
        int nt = r % 6; int w8 = r / 6;
        int g = nt >> 1, s = nt & 1;
        int n = g * 128 + w8 * 16 + s * 8 + (lane >> 2);
        int kb = (lane & 3) * 2;
        float w0 = Wih[n * FF + kb],     w1 = Wih[n * FF + kb + 1];
        float w2 = Wih[n * FF + kb + 8], w3 = Wih[n * FF + kb + 9];
        __nv_bfloat16 h0 = __float2bfloat16(w0), h1 = __float2bfloat16(w1);
        __nv_bfloat16 h2 = __float2bfloat16(w2), h3 = __float2bfloat16(w3);
        {
            __nv_bfloat162 v; v.x = h0; v.y = h1;
            g_WihHi[idx * 2 + 0] = *(uint32_t*)&v;
            v.x = h2; v.y = h3;
            g_WihHi[idx * 2 + 1] = *(uint32_t*)&v;
        }
        __nv_bfloat162 l01, l23;
        l01.x = __float2bfloat16(w0 - __bfloat162float(h0));
        l01.y = __float2bfloat16(w1 - __bfloat162float(h1));
        l23.x = __float2bfloat16(w2 - __bfloat162float(h2));
        l23.y = __float2bfloat16(w3 - __bfloat162float(h3));
        uint32_t* lo = &g_WihLo[((w8 * 2 + s) * 32 + lane) * 8 + g * 2];
        lo[0] = *(uint32_t*)&l01;
        lo[1] = *(uint32_t*)&l23;
        if (blk == 48 && threadIdx.x < HH) g_colsum[threadIdx.x] = 0.f;
    }
}

// ---------------- kernel 2: fused GRU, 256 thr, B-hi in registers -----------
#define HBUF 2176

__global__ void __launch_bounds__(256, 1) k_gru(const float* __restrict__ feat,
                                                const float* __restrict__ bih,
                                                const float* __restrict__ bhh) {
    __shared__ __align__(16) uint32_t hbase[4 * HBUF];   // 34.8 KB
    int tid = threadIdx.x;
    int w = tid >> 5, lane = tid & 31;
    int qr = lane >> 2, qc = lane & 3;
    int node0 = blockIdx.x * 32;

    const uint2* Bhi2g = (const uint2*)g_Bhi;
    uint2 bhr[8][3][2];
#pragma unroll
    for (int kt = 0; kt < 8; kt++)
#pragma unroll
        for (int g = 0; g < 3; g++)
#pragma unroll
            for (int s = 0; s < 2; s++)
                bhr[kt][g][s] = __ldg(&Bhi2g[((kt * 8 + w) * 6 + g * 2 + s) * 32 + lane]);

    for (int i = tid; i < 4 * HBUF; i += 256) hbase[i] = 0u;

    float bRr[2][2], bRz[2][2], biN[2][2], bhN[2][2];
#pragma unroll
    for (int s = 0; s < 2; s++)
#pragma unroll
        for (int jj = 0; jj < 2; jj++) {
            int c = w * 16 + s * 8 + 2 * qc + jj;
            bRr[s][jj] = __ldg(&bih[c]) + __ldg(&bhh[c]);
            bRz[s][jj] = __ldg(&bih[128 + c]) + __ldg(&bhh[128 + c]);
            biN[s][jj] = __ldg(&bih[256 + c]);
            bhN[s][jj] = __ldg(&bhh[256 + c]);
        }
    __syncthreads();

    const uint2* WihHi2 = (const uint2*)g_WihHi;
    int cur = 0;

    for (int t = 0; t < TT; t++) {
        uint32_t* h_hi_w = hbase + cur * (2 * HBUF);
        uint32_t* h_lo_w = h_hi_w + HBUF;
        uint32_t* n_hi_w = hbase + (cur ^ 1) * (2 * HBUF);
        uint32_t* n_lo_w = n_hi_w + HBUF;

        uint32_t xh[2][4], xl[2][4];
#pragma unroll
        for (int m = 0; m < 2; m++) {
            const float* base = feat + (size_t)(node0 + m * 16) * (TT * FF) + t * FF;
            float2 v[4];
            v[0] = __ldg((const float2*)(base + (size_t)qr * (TT * FF) + 2 * qc));
            v[1] = __ldg((const float2*)(base + (size_t)(qr + 8) * (TT * FF) + 2 * qc));
            v[2] = __ldg((const float2*)(base + (size_t)qr * (TT * FF) + 2 * qc + 8));
            v[3] = __ldg((const float2*)(base + (size_t)(qr + 8) * (TT * FF) + 2 * qc + 8));
#pragma unroll
            for (int j = 0; j < 4; j++) {
                __nv_bfloat162 hv; hv.x = __float2bfloat16(v[j].x); hv.y = __float2bfloat16(v[j].y);
                xh[m][j] = *(uint32_t*)&hv;
                __nv_bfloat162 lv;
                lv.x = __float2bfloat16(v[j].x - __bfloat162float(hv.x));
                lv.y = __float2bfloat16(v[j].y - __bfloat162float(hv.y));
                xl[m][j] = *(uint32_t*)&lv;
            }
        }

        float d[2][3][2][4];
        float dx[2][2][4];
#pragma unroll
        for (int m = 0; m < 2; m++) {
#pragma unroll
            for (int g = 0; g < 3; g++)
#pragma unroll
                for (int s = 0; s < 2; s++)
#pragma unroll
                    for (int j = 0; j < 4; j++) d[m][g][s][j] = 0.f;
#pragma unroll
            for (int s = 0; s < 2; s++)
#pragma unroll
                for (int j = 0; j < 4; j++) dx[m][s][j] = 0.f;
        }

        // ---- x @ Wih^T (k=16) ----
#pragma unroll
        for (int s = 0; s < 2; s++) {
            const uint32_t* p = &g_WihLo[((w * 2 + s) * 32 + lane) * 8];
            uint4 wlA = __ldg((const uint4*)p);
            uint2 wlB = __ldg((const uint2*)(p + 4));
            uint32_t wlw[6] = {wlA.x, wlA.y, wlA.z, wlA.w, wlB.x, wlB.y};
#pragma unroll
            for (int g = 0; g < 3; g++) {
                uint2 bh = __ldg(&WihHi2[(w * 6 + g * 2 + s) * 32 + lane]);
#pragma unroll
                for (int m = 0; m < 2; m++) {
                    float* D = (g == 2) ? dx[m][s] : d[m][g][s];
                    mma_bf16(D, xh[m], bh.x, bh.y);
                    mma_bf16(D, xl[m], bh.x, bh.y);
                    mma_bf16(D, xh[m], wlw[g * 2], wlw[g * 2 + 1]);
                }
            }
        }

        // ---- h @ Whh^T (bf16, B-hi from registers, lo streamed) ----
        if (t) {
#pragma unroll
            for (int kt = 0; kt < 8; kt++) {
                uint32_t ah[2][4], al[2][4];
#pragma unroll
                for (int m = 0; m < 2; m++) {
                    int r0 = (m * 16 + qr) * 68 + kt * 8 + qc;
                    ah[m][0] = h_hi_w[r0];
                    ah[m][1] = h_hi_w[r0 + 8 * 68];
                    ah[m][2] = h_hi_w[r0 + 4];
                    ah[m][3] = h_hi_w[r0 + 8 * 68 + 4];
                    al[m][0] = h_lo_w[r0];
                    al[m][1] = h_lo_w[r0 + 8 * 68];
                    al[m][2] = h_lo_w[r0 + 4];
                    al[m][3] = h_lo_w[r0 + 8 * 68 + 4];
                }
#pragma unroll
                for (int s = 0; s < 2; s++) {
                    const uint32_t* p = &g_Blo[(((kt * 8 + w) * 2 + s) * 32 + lane) * 8];
                    uint4 lA = __ldg((const uint4*)p);
                    uint2 lB = __ldg((const uint2*)(p + 4));
                    uint32_t lw[6] = {lA.x, lA.y, lA.z, lA.w, lB.x, lB.y};
#pragma unroll
                    for (int g = 0; g < 3; g++) {
                        uint2 bh = bhr[kt][g][s];
#pragma unroll
                        for (int m = 0; m < 2; m++) {
                            mma_bf16(d[m][g][s], ah[m], bh.x, bh.y);
                            mma_bf16(d[m][g][s], al[m], bh.x, bh.y);
                            mma_bf16(d[m][g][s], ah[m], lw[g * 2], lw[g * 2 + 1]);
                        }
                    }
                }
            }
        }

        // ---- gate math: read h[cur], write h[nxt], single barrier ----
#pragma unroll
        for (int m = 0; m < 2; m++)
#pragma unroll
            for (int s = 0; s < 2; s++)
#pragma unroll
                for (int rg = 0; rg < 2; rg++) {
                    int row = m * 16 + qr + rg * 8;
                    int wi = row * 68 + w * 8 + s * 4 + qc;
                    float2 hhf = __bfloat1622float2(*(__nv_bfloat162*)&h_hi_w[wi]);
                    float2 hlf = __bfloat1622float2(*(__nv_bfloat162*)&h_lo_w[wi]);
                    float hn[2];
#pragma unroll
                    for (int jj = 0; jj < 2; jj++) {
                        float hold = jj ? (hhf.y + hlf.y) : (hhf.x + hlf.x);
                        int di = rg * 2 + jj;
                        float rr = sigmoid_fast(d[m][0][s][di] + bRr[s][jj]);
                        float zz = sigmoid_fast(d[m][1][s][di] + bRz[s][jj]);
                        float nv = tanh_fast(dx[m][s][di] + biN[s][jj] +
                                             rr * (d[m][2][s][di] + bhN[s][jj]));
                        hn[jj] = (1.f - zz) * nv + zz * hold;
                    }
                    __nv_bfloat162 hv; hv.x = __float2bfloat16(hn[0]); hv.y = __float2bfloat16(hn[1]);
                    __nv_bfloat162 lv;
                    lv.x = __float2bfloat16(hn[0] - __bfloat162float(hv.x));
                    lv.y = __float2bfloat16(hn[1] - __bfloat162float(hv.y));
                    n_hi_w[wi] = *(uint32_t*)&hv;
                    n_lo_w[wi] = *(uint32_t*)&lv;
                }
        __syncthreads();
        cur ^= 1;
    }

    const __nv_bfloat16* h_hi = (const __nv_bfloat16*)(hbase + cur * (2 * HBUF));
    const __nv_bfloat16* h_lo = h_hi + 2 * HBUF;
    for (int i = tid; i < 32 * HH; i += 256) {
        int row = i >> 7, col = i & 127;
        g_support[(size_t)(node0 + row) * HH + col] =
            __bfloat162float(h_hi[row * 136 + col]) +
            __bfloat162float(h_lo[row * 136 + col]);
    }
}

// ---------------- kernel 3: bf16 GEMM C = A @ B (+b1+b2) [+f1/f2 epilogue] --
struct GemmJob {
    const float* A; const float* B; const float* b1; const float* b2; float* C;
    const float* u; const float* v; float* f1; float* f2;
};
struct GemmJobs { GemmJob j[5]; };

#define GEMM_SMEM (4 * 128 * 136 * 2)   // 139264 B

__global__ void __launch_bounds__(256) k_gemm(GemmJobs jobs) {
    GemmJob job = jobs.j[blockIdx.y];
    extern __shared__ char smc[];
    uint16_t* As_hi = (uint16_t*)smc;
    uint16_t* As_lo = As_hi + 128 * 136;
    uint16_t* Bs_hi = As_lo + 128 * 136;
    uint16_t* Bs_lo = Bs_hi + 128 * 136;
    int tid = threadIdx.x;
    int node0 = blockIdx.x * 128;

    for (int idx = tid; idx < 128 * 128; idx += 256) {
        int r = idx >> 7, c = idx & 127;
        float a = job.A[(size_t)(node0 + r) * HH + c];
        __nv_bfloat16 ah = __float2bfloat16(a);
        As_hi[r * 136 + c] = __bfloat16_as_ushort(ah);
        As_lo[r * 136 + c] =
            __bfloat16_as_ushort(__float2bfloat16(a - __bfloat162float(ah)));
        float b = job.B[idx];
        __nv_bfloat16 bh = __float2bfloat16(b);
        Bs_hi[c * 136 + r] = __bfloat16_as_ushort(bh);
        Bs_lo[c * 136 + r] =
            __bfloat16_as_ushort(__float2bfloat16(b - __bfloat162float(bh)));
    }
    __syncthreads();

    int w = tid >> 5, lane = tid & 31;
    int qr = lane >> 2, qc = lane & 3;
    int r0 = w * 16;
    const uint32_t* Aw_hi = (const uint32_t*)As_hi;
    const uint32_t* Aw_lo = (const uint32_t*)As_lo;
    const uint32_t* Bw_hi = (const uint32_t*)Bs_hi;
    const uint32_t* Bw_lo = (const uint32_t*)Bs_lo;

    float acc[16][4];
#pragma unroll
    for (int ct = 0; ct < 16; ct++)
#pragma unroll
        for (int j = 0; j < 4; j++) acc[ct][j] = 0.f;

#pragma unroll 1
    for (int kt = 0; kt < 8; kt++) {
        int kc = kt * 8 + qc;
        uint32_t ah[4], al[4];
        ah[0] = Aw_hi[(r0 + qr) * 68 + kc];
        ah[1] = Aw_hi[(r0 + qr + 8) * 68 + kc];
        ah[2] = Aw_hi[(r0 + qr) * 68 + kc + 4];
        ah[3] = Aw_hi[(r0 + qr + 8) * 68 + kc + 4];
        al[0] = Aw_lo[(r0 + qr) * 68 + kc];
        al[1] = Aw_lo[(r0 + qr + 8) * 68 + kc];
        al[2] = Aw_lo[(r0 + qr) * 68 + kc + 4];
        al[3] = Aw_lo[(r0 + qr + 8) * 68 + kc + 4];
#pragma unroll
        for (int cg = 0; cg < 4; cg++) {
            uint32_t bh0[4], bh1[4], bl0[4], bl1[4];
#pragma unroll
            for (int j = 0; j < 4; j++) {
                int n0 = (cg * 4 + j) * 8;
                bh0[j] = Bw_hi[(n0 + qr) * 68 + kc];
                bh1[j] = Bw_hi[(n0 + qr) * 68 + kc + 4];
                bl0[j] = Bw_lo[(n0 + qr) * 68 + kc];
                bl1[j] = Bw_lo[(n0 + qr) * 68 + kc + 4];
            }
#pragma unroll
            for (int j = 0; j < 4; j++)
                mma_bf16(acc[cg * 4 + j], ah, bh0[j], bh1[j]);
#pragma unroll
            for (int j = 0; j < 4; j++)
                mma_bf16(acc[cg * 4 + j], al, bh0[j], bh1[j]);
#pragma unroll
            for (int j = 0; j < 4; j++)
                mma_bf16(acc[cg * 4 + j], ah, bl0[j], bl1[j]);
        }
    }

#pragma unroll
    for (int ct = 0; ct < 16; ct++) {
        int c0 = ct * 8 + 2 * qc;
        float b0 = 0.f, b1v = 0.f;
        if (job.b1) { b0 += __ldg(&job.b1[c0]); b1v += __ldg(&job.b1[c0 + 1]); }
        if (job.b2) { b0 += __ldg(&job.b2[c0]); b1v += __ldg(&job.b2[c0 + 1]); }
        acc[ct][0] += b0; acc[ct][1] += b1v;
        acc[ct][2] += b0; acc[ct][3] += b1v;
        int r = node0 + r0 + qr;
        *(float2*)&job.C[(size_t)r * HH + c0] = make_float2(acc[ct][0], acc[ct][1]);
        *(float2*)&job.C[(size_t)(r + 8) * HH + c0] = make_float2(acc[ct][2], acc[ct][3]);
    }

    // ---- fused f1/f2 epilogue (attention logits per head) ----
    if (job.u) {
        float f1p[2][4], f2p[2][4];
#pragma unroll
        for (int rh = 0; rh < 2; rh++)
#pragma unroll
            for (int h = 0; h < 4; h++) { f1p[rh][h] = 0.f; f2p[rh][h] = 0.f; }
#pragma unroll
        for (int ct = 0; ct < 16; ct++) {
            int h = ct >> 2;
            int c0 = ct * 8 + 2 * qc;
            float u0 = __ldg(&job.u[c0]),     u1 = __ldg(&job.u[c0 + 1]);
            float v0 = __ldg(&job.v[c0]),     v1 = __ldg(&job.v[c0 + 1]);
            f1p[0][h] += acc[ct][0] * u0 + acc[ct][1] * u1;
            f2p[0][h] += acc[ct][0] * v0 + acc[ct][1] * v1;
            f1p[1][h] += acc[ct][2] * u0 + acc[ct][3] * u1;
            f2p[1][h] += acc[ct][2] * v0 + acc[ct][3] * v1;
        }
#pragma unroll
        for (int rh = 0; rh < 2; rh++)
#pragma unroll
            for (int h = 0; h < 4; h++) {
                f1p[rh][h] += __shfl_xor_sync(0xffffffffu, f1p[rh][h], 1);
                f1p[rh][h] += __shfl_xor_sync(0xffffffffu, f1p[rh][h], 2);
                f2p[rh][h] += __shfl_xor_sync(0xffffffffu, f2p[rh][h], 1);
                f2p[rh][h] += __shfl_xor_sync(0xffffffffu, f2p[rh][h], 2);
            }
        if (qc == 0) {
#pragma unroll
            for (int rh = 0; rh < 2; rh++) {
                int r = node0 + r0 + qr + rh * 8;
#pragma unroll
                for (int h = 0; h < 4; h++) {
                    job.f1[h * NN + r] = f1p[rh][h];
                    job.f2[h * NN + r] = f2p[rh][h];
                }
            }
        }
    }
}

// ---------------- kernel 5: GAT aggregation, bulk-copy scan ------------------
__global__ void __launch_bounds__(128) k_gat(const float* __restrict__ adjP,
                                             const float* __restrict__ adjN) {
    __shared__ __align__(128) float tile[NN];        // 16 KB adjacency row
    __shared__ __align__(8) uint64_t mbar;
    __shared__ int s_cnt;
    __shared__ int s_list[640];
    __shared__ float s_a[640];
    const float* adj; const float* sup; const float* f1; const float* f2;
    const float* resid; float* outp;
    if (blockIdx.y == 0) { adj = adjP; sup = g_supP; f1 = g_f1P; f2 = g_f2P; resid = g_residP; outp = g_gatP; }
    else                 { adj = adjN; sup = g_supN; f1 = g_f1N; f2 = g_f2N; resid = g_residN; outp = g_gatN; }
    int i = blockIdx.x, tid = threadIdx.x;
    int h = tid >> 5;

    uint32_t tile_a = (uint32_t)__cvta_generic_to_shared(tile);
    uint32_t mbar_a = (uint32_t)__cvta_generic_to_shared(&mbar);
    if (tid == 0) {
        s_cnt = 0;
        asm volatile("mbarrier.init.shared.b64 [%0], 1;" :: "r"(mbar_a) : "memory");
        asm volatile("fence.proxy.async.shared::cta;" ::: "memory");
        asm volatile("mbarrier.arrive.expect_tx.shared.b64 _, [%0], %1;"
                     :: "r"(mbar_a), "r"((uint32_t)(NN * 4)) : "memory");
        asm volatile("cp.async.bulk.shared::cta.global.mbarrier::complete_tx::bytes "
                     "[%0], [%1], %2, [%3];"
                     :: "r"(tile_a), "l"(adj + (size_t)i * NN),
                        "r"((uint32_t)(NN * 4)), "r"(mbar_a) : "memory");
    }
    __syncthreads();
    // all threads wait for bulk-copy completion (phase 0, acquire)
    {
        uint32_t done;
        do {
            asm volatile("{\n\t.reg .pred p;\n\t"
                         "mbarrier.try_wait.parity.acquire.cta.shared::cta.b64 p, [%1], %2;\n\t"
                         "selp.b32 %0, 1, 0, p;\n\t}"
                         : "=r"(done) : "r"(mbar_a), "r"(0u) : "memory");
        } while (!done);
    }

    // scan from shared (LDS.128 instead of LDG.128: 3.6x lower issue cost)
    const float4* t4 = (const float4*)tile;
    for (int j4 = tid; j4 < NN / 4; j4 += 128) {
        float4 a = t4[j4];
        if (a.x != 0.f) { int p = atomicAdd(&s_cnt, 1); s_list[p] = j4 * 4 + 0; s_a[p] = a.x; }
        if (a.y != 0.f) { int p = atomicAdd(&s_cnt, 1); s_list[p] = j4 * 4 + 1; s_a[p] = a.y; }
        if (a.z != 0.f) { int p = atomicAdd(&s_cnt, 1); s_list[p] = j4 * 4 + 2; s_a[p] = a.z; }
        if (a.w != 0.f) { int p = atomicAdd(&s_cnt, 1); s_list[p] = j4 * 4 + 3; s_a[p] = a.w; }
    }
    __syncthreads();
    int cnt = s_cnt;
    float f2i = f2[h * NN + i];
    float num = 0.f, den = 0.f;
    for (int t = 0; t < cnt; t++) {
        int j = s_list[t];
        float wv = f1[h * NN + j] + f2i;
        wv = ((wv > 0.f) ? wv : 0.2f * wv) * s_a[t];
        den += wv;
        num += wv * sup[(size_t)j * HH + tid];
    }
    float d = (den == 0.f) ? 1.f : den;
    outp[(size_t)i * HH + tid] = num / d + resid[(size_t)i * HH + tid];
}

// ---------------- kernel 7: semantic attention, warp-per-node ----------------
__global__ void __launch_bounds__(256) k_sem(const float* __restrict__ W1,
                                             const float* __restrict__ b1,
                                             const float* __restrict__ W2) {
    __shared__ float W1s[128 * 65];
    __shared__ float W2s[SEMD], b1s[SEMD];
    __shared__ float semb[8][3][128];
    int tid = threadIdx.x;
    for (int i = tid; i < 128 * 64; i += 256) {
        int k = i >> 6, s = i & 63;
        W1s[k * 65 + s] = W1[i];
    }
    if (tid < SEMD) { W2s[tid] = W2[tid]; b1s[tid] = b1[tid]; }
    __syncthreads();

    int w = tid >> 5, lane = tid & 31;
    float csum[4] = {0.f, 0.f, 0.f, 0.f};
    int nbase = (blockIdx.x * 8 + w) * 8;

    for (int i = 0; i < 8; i++) {
        int n = nbase + i;
        float4 ev[3];
        ev[0] = *(const float4*)&g_selfE[(size_t)n * HH + lane * 4];
        ev[1] = *(const float4*)&g_posE[(size_t)n * HH + lane * 4];
        ev[2] = *(const float4*)&g_negE[(size_t)n * HH + lane * 4];
        __syncwarp();
        *(float4*)&semb[w][0][lane * 4] = ev[0];
        *(float4*)&semb[w][1][lane * 4] = ev[1];
        *(float4*)&semb[w][2][lane * 4] = ev[2];
        __syncwarp();

        float acc[3][2];
#pragma unroll
        for (int e = 0; e < 3; e++) { acc[e][0] = b1s[lane]; acc[e][1] = b1s[lane + 32]; }
#pragma unroll 4
        for (int k = 0; k < HH; k++) {
            float w1a = W1s[k * 65 + lane];
            float w1b = W1s[k * 65 + lane + 32];
            float x0 = semb[w][0][k], x1 = semb[w][1][k], x2 = semb[w][2][k];
            acc[0][0] += x0 * w1a; acc[0][1] += x0 * w1b;
            acc[1][0] += x1 * w1a; acc[1][1] += x1 * w1b;
            acc[2][0] += x2 * w1a; acc[2][1] += x2 * w1b;
        }
        float wv[3];
#pragma unroll
        for (int e = 0; e < 3; e++) {
            float tsum = tanh_fast(acc[e][0]) * W2s[lane] +
                         tanh_fast(acc[e][1]) * W2s[lane + 32];
            wv[e] = warpsum_bfly(tsum);
        }
        float m = fmaxf(wv[0], fmaxf(wv[1], wv[2]));
        float e0 = __expf(wv[0] - m), e1 = __expf(wv[1] - m), e2 = __expf(wv[2] - m);
        float inv = __fdividef(1.f, e0 + e1 + e2);
        float be0 = e0 * inv, be1 = e1 * inv, be2 = e2 * inv;
        float4 f;
        f.x = be0 * ev[0].x + be1 * ev[1].x + be2 * ev[2].x;
        f.y = be0 * ev[0].y + be1 * ev[1].y + be2 * ev[2].y;
        f.z = be0 * ev[0].z + be1 * ev[1].z + be2 * ev[2].z;
        f.w = be0 * ev[0].w + be1 * ev[1].w + be2 * ev[2].w;
        *(float4*)&g_fused[(size_t)n * HH + lane * 4] = f;
        csum[0] += f.x; csum[1] += f.y; csum[2] += f.z; csum[3] += f.w;
    }
    atomicAdd(&g_colsum[lane * 4 + 0], csum[0]);
    atomicAdd(&g_colsum[lane * 4 + 1], csum[1]);
    atomicAdd(&g_colsum[lane * 4 + 2], csum[2]);
    atomicAdd(&g_colsum[lane * 4 + 3], csum[3]);
}

// ---------------- kernel 8: pairnorm + predictor -----------------------------
__global__ void __launch_bounds__(256) k_pred(const float* __restrict__ W1,
                                              const float* __restrict__ b1,
                                              const float* __restrict__ W2,
                                              const float* __restrict__ b2,
                                              float* __restrict__ out) {
    __shared__ float W1s[HH * PHD];
    __shared__ float xns[8][HH];
    int tid = threadIdx.x;
    for (int i = tid; i < HH * PHD; i += 256) W1s[i] = W1[i];
    int w = tid >> 5, lane = tid & 31;
    int n = blockIdx.x * 8 + w;
    float xv[4]; float ss = 0.f;
    const float invN = 1.f / (float)NN;
#pragma unroll
    for (int j = 0; j < 4; j++) {
        int d = lane + j * 32;
        float x = g_fused[(size_t)n * HH + d] - g_colsum[d] * invN;
        xv[j] = x; ss += x * x;
    }
    ss = warpsum(ss);
    ss = __shfl_sync(0xffffffffu, ss, 0);
    float rinv = rsqrtf(1e-6f + ss);
#pragma unroll
    for (int j = 0; j < 4; j++) xns[w][lane + j * 32] = xv[j] * rinv;
    __syncthreads();

    float acc = b1[lane];
#pragma unroll 4
    for (int k = 0; k < HH; k++) acc += xns[w][k] * W1s[k * PHD + lane];
    float hgt = acc > 0.f ? acc : 0.f;
    float o = warpsum(hgt * W2[lane]);
    if (lane == 0) out[n] = sigmoid_fast(o + b2[0]);
}

// ---------------- launch -----------------------------------------------------
extern "C" void kernel_launch(void* const* d_in, const int* in_sizes, int n_in,
                              void* d_out, int out_size) {
    const float* features = (const float*)d_in[0];
    const float* pos_adj  = (const float*)d_in[1];
    const float* neg_adj  = (const float*)d_in[2];
    const float* gru_Wih  = (const float*)d_in[3];
    const float* gru_Whh  = (const float*)d_in[4];
    const float* gru_bih  = (const float*)d_in[5];
    const float* gru_bhh  = (const float*)d_in[6];
    const float* pos_W    = (const float*)d_in[7];
    const float* pos_u    = (const float*)d_in[8];
    const float* pos_v    = (const float*)d_in[9];
    const float* pos_b    = (const float*)d_in[10];
    const float* pos_pW   = (const float*)d_in[11];
    const float* pos_pb   = (const float*)d_in[12];
    const float* neg_W    = (const float*)d_in[13];
    const float* neg_u    = (const float*)d_in[14];
    const float* neg_v    = (const float*)d_in[15];
    const float* neg_b    = (const float*)d_in[16];
    const float* neg_pW   = (const float*)d_in[17];
    const float* neg_pb   = (const float*)d_in[18];
    const float* self_W   = (const float*)d_in[19];
    const float* self_b   = (const float*)d_in[20];
    const float* mpos_W   = (const float*)d_in[21];
    const float* mpos_b   = (const float*)d_in[22];
    const float* mneg_W   = (const float*)d_in[23];
    const float* mneg_b   = (const float*)d_in[24];
    const float* sem_W1   = (const float*)d_in[25];
    const float* sem_b1   = (const float*)d_in[26];
    const float* sem_W2   = (const float*)d_in[27];
    const float* pred_W1  = (const float*)d_in[28];
    const float* pred_b1  = (const float*)d_in[29];
    const float* pred_W2  = (const float*)d_in[30];
    const float* pred_b2  = (const float*)d_in[31];
    float* out = (float*)d_out;

    static bool attr_done = false;
    if (!attr_done) {
        cudaFuncSetAttribute(k_gemm, cudaFuncAttributeMaxDynamicSharedMemorySize, GEMM_SMEM);
        attr_done = true;
    }

    float *p_support, *p_gatP, *p_gatN, *p_supP, *p_supN;
    float *p_residP, *p_residN, *p_selfE, *p_posE, *p_negE;
    float *p_f1P, *p_f2P, *p_f1N, *p_f2N;
    cudaGetSymbolAddress((void**)&p_support, g_support);
    cudaGetSymbolAddress((void**)&p_supP, g_supP);
    cudaGetSymbolAddress((void**)&p_supN, g_supN);
    cudaGetSymbolAddress((void**)&p_residP, g_residP);
    cudaGetSymbolAddress((void**)&p_residN, g_residN);
    cudaGetSymbolAddress((void**)&p_selfE, g_selfE);
    cudaGetSymbolAddress((void**)&p_gatP, g_gatP);
    cudaGetSymbolAddress((void**)&p_gatN, g_gatN);
    cudaGetSymbolAddress((void**)&p_posE, g_posE);
    cudaGetSymbolAddress((void**)&p_negE, g_negE);
    cudaGetSymbolAddress((void**)&p_f1P, g_f1P);
    cudaGetSymbolAddress((void**)&p_f2P, g_f2P);
    cudaGetSymbolAddress((void**)&p_f1N, g_f1N);
    cudaGetSymbolAddress((void**)&p_f2N, g_f2N);

    k_prep_all<<<54, 256>>>(gru_Whh, gru_Wih);                      // 1
    k_gru<<<NN / 32, 256>>>(features, gru_bih, gru_bhh);            // 2
    {
        GemmJobs jb;
        jb.j[0] = { p_support, pos_W,  nullptr, nullptr, p_supP, pos_u, pos_v, p_f1P, p_f2P };
        jb.j[1] = { p_support, neg_W,  nullptr, nullptr, p_supN, neg_u, neg_v, p_f1N, p_f2N };
        jb.j[2] = { p_support, pos_pW, pos_b,   pos_pb,  p_residP, nullptr, nullptr, nullptr, nullptr };
        jb.j[3] = { p_support, neg_pW, neg_b,   neg_pb,  p_residN, nullptr, nullptr, nullptr, nullptr };
        jb.j[4] = { p_support, self_W, self_b,  nullptr, p_selfE, nullptr, nullptr, nullptr, nullptr };
        dim3 grid(NN / 128, 5);
        k_gemm<<<grid, 256, GEMM_SMEM>>>(jb);                       // 3
    }
    {
        dim3 grid(NN, 2);
        k_gat<<<grid, 128>>>(pos_adj, neg_adj);                     // 4
    }
    {
        GemmJobs jb;
        jb.j[0] = { p_gatP, mpos_W, mpos_b, nullptr, p_posE, nullptr, nullptr, nullptr, nullptr };
        jb.j[1] = { p_gatN, mneg_W, mneg_b, nullptr, p_negE, nullptr, nullptr, nullptr, nullptr };
        jb.j[2] = jb.j[0]; jb.j[3] = jb.j[0]; jb.j[4] = jb.j[0];
        dim3 grid(NN / 128, 2);
        k_gemm<<<grid, 256, GEMM_SMEM>>>(jb);                       // 5
    }
    k_sem<<<NN / 64, 256>>>(sem_W1, sem_b1, sem_W2);                // 6
    k_pred<<<NN / 8, 256>>>(pred_W1, pred_b1, pred_W2, pred_b2, out); // 7
}

// round 17
// speedup vs baseline: 1.0691x; 1.0374x over previous
#include <cuda_runtime.h>
#include <cuda_bf16.h>
#include <cstdint>
#include <cstddef>

#define NN 4096
#define TT 24
#define FF 16
#define HH 128
#define GG 384
#define NHD 4
#define DOD 32
#define SEMD 64
#define PHD 32

// ---------------- scratch (static device globals; no runtime allocation) ----
__device__ float g_support[NN * HH];
__device__ float g_supP[NN * HH];
__device__ float g_supN[NN * HH];
__device__ float g_residP[NN * HH];
__device__ float g_residN[NN * HH];
__device__ float g_selfE[NN * HH];
__device__ float g_f1P[NHD * NN];
__device__ float g_f2P[NHD * NN];
__device__ float g_f1N[NHD * NN];
__device__ float g_f2N[NHD * NN];
__device__ float g_gatP[NN * HH];
__device__ float g_gatN[NN * HH];
__device__ float g_posE[NN * HH];
__device__ float g_negE[NN * HH];
__device__ float g_fused[NN * HH];
__device__ float g_colsum[HH];
// bf16 fragment-ordered Whh: hi (register-staged per warp), lo (streamed)
__device__ __align__(16) uint32_t g_Bhi[8 * 8 * 6 * 32 * 2];   // 24576 words
__device__ __align__(16) uint32_t g_Blo[8 * 8 * 2 * 32 * 8];   // 32768 words
// bf16 fragment-ordered Wih (k=16 -> one k-chunk)
__device__ __align__(16) uint32_t g_WihHi[8 * 6 * 32 * 2];
__device__ __align__(16) uint32_t g_WihLo[8 * 2 * 32 * 8];

__device__ __forceinline__ float warpsum(float v) {
#pragma unroll
    for (int o = 16; o >= 1; o >>= 1) v += __shfl_down_sync(0xffffffffu, v, o);
    return v;
}
__device__ __forceinline__ float warpsum_bfly(float v) {
#pragma unroll
    for (int o = 16; o >= 1; o >>= 1) v += __shfl_xor_sync(0xffffffffu, v, o);
    return v;
}
__device__ __forceinline__ float sigmoid_fast(float x) {
    return __fdividef(1.f, 1.f + __expf(-x));
}
__device__ __forceinline__ float tanh_fast(float x) {
    float e = __expf(-2.f * x);
    return __fdividef(2.f, 1.f + e) - 1.f;
}
__device__ __forceinline__ void mma_bf16(float d[4], const uint32_t a[4],
                                         uint32_t b0, uint32_t b1) {
    asm volatile("mma.sync.aligned.m16n8k16.row.col.f32.bf16.bf16.f32 "
                 "{%0,%1,%2,%3}, {%4,%5,%6,%7}, {%8,%9}, {%0,%1,%2,%3};"
                 : "+f"(d[0]), "+f"(d[1]), "+f"(d[2]), "+f"(d[3])
                 : "r"(a[0]), "r"(a[1]), "r"(a[2]), "r"(a[3]), "r"(b0), "r"(b1));
}

// ---------------- kernel 0: combined prep (Whh + Wih + colsum zero) ---------
__global__ void k_prep_all(const float* __restrict__ Whh,
                           const float* __restrict__ Wih) {
    int blk = blockIdx.x;
    if (blk < 48) {
        int idx = blk * 256 + threadIdx.x;           // 12288 = 8*8*6*32
        int lane = idx & 31; int r = idx >> 5;
        int nt = r % 6; r /= 6;
        int w8 = r & 7; int kt = r >> 3;
        int g = nt >> 1, s = nt & 1;
        int n = g * 128 + w8 * 16 + s * 8 + (lane >> 2);
        int kb = kt * 16 + (lane & 3) * 2;
        float w0 = Whh[n * 128 + kb],     w1 = Whh[n * 128 + kb + 1];
        float w2 = Whh[n * 128 + kb + 8], w3 = Whh[n * 128 + kb + 9];
        __nv_bfloat16 h0 = __float2bfloat16(w0), h1 = __float2bfloat16(w1);
        __nv_bfloat16 h2 = __float2bfloat16(w2), h3 = __float2bfloat16(w3);
        {
            __nv_bfloat162 v; v.x = h0; v.y = h1;
            g_Bhi[idx * 2 + 0] = *(uint32_t*)&v;
            v.x = h2; v.y = h3;
            g_Bhi[idx * 2 + 1] = *(uint32_t*)&v;
        }
        __nv_bfloat162 l01, l23;
        l01.x = __float2bfloat16(w0 - __bfloat162float(h0));
        l01.y = __float2bfloat16(w1 - __bfloat162float(h1));
        l23.x = __float2bfloat16(w2 - __bfloat162float(h2));
        l23.y = __float2bfloat16(w3 - __bfloat162float(h3));
        uint32_t* lo = &g_Blo[(((kt * 8 + w8) * 2 + s) * 32 + lane) * 8 + g * 2];
        lo[0] = *(uint32_t*)&l01;
        lo[1] = *(uint32_t*)&l23;
    } else {
        int idx = (blk - 48) * 256 + threadIdx.x;    // 1536 = 8*6*32
        int lane = idx & 31; int r = idx >> 5;
        int nt = r % 6; int w8 = r / 6;
        int g = nt >> 1, s = nt & 1;
        int n = g * 128 + w8 * 16 + s * 8 + (lane >> 2);
        int kb = (lane & 3) * 2;
        float w0 = Wih[n * FF + kb],     w1 = Wih[n * FF + kb + 1];
        float w2 = Wih[n * FF + kb + 8], w3 = Wih[n * FF + kb + 9];
        __nv_bfloat16 h0 = __float2bfloat16(w0), h1 = __float2bfloat16(w1);
        __nv_bfloat16 h2 = __float2bfloat16(w2), h3 = __float2bfloat16(w3);
        {
            __nv_bfloat162 v; v.x = h0; v.y = h1;
            g_WihHi[idx * 2 + 0] = *(uint32_t*)&v;
            v.x = h2; v.y = h3;
            g_WihHi[idx * 2 + 1] = *(uint32_t*)&v;
        }
        __nv_bfloat162 l01, l23;
        l01.x = __float2bfloat16(w0 - __bfloat162float(h0));
        l01.y = __float2bfloat16(w1 - __bfloat162float(h1));
        l23.x = __float2bfloat16(w2 - __bfloat162float(h2));
        l23.y = __float2bfloat16(w3 - __bfloat162float(h3));
        uint32_t* lo = &g_WihLo[((w8 * 2 + s) * 32 + lane) * 8 + g * 2];
        lo[0] = *(uint32_t*)&l01;
        lo[1] = *(uint32_t*)&l23;
        if (blk == 48 && threadIdx.x < HH) g_colsum[threadIdx.x] = 0.f;
    }
}

// ---------------- kernel 2: fused GRU, 256 thr, B-hi in registers -----------
#define HBUF 2176

__global__ void __launch_bounds__(256, 1) k_gru(const float* __restrict__ feat,
                                                const float* __restrict__ bih,
                                                const float* __restrict__ bhh) {
    __shared__ __align__(16) uint32_t hbase[4 * HBUF];   // 34.8 KB
    int tid = threadIdx.x;
    int w = tid >> 5, lane = tid & 31;
    int qr = lane >> 2, qc = lane & 3;
    int node0 = blockIdx.x * 32;

    const uint2* Bhi2g = (const uint2*)g_Bhi;
    uint2 bhr[8][3][2];
#pragma unroll
    for (int kt = 0; kt < 8; kt++)
#pragma unroll
        for (int g = 0; g < 3; g++)
#pragma unroll
            for (int s = 0; s < 2; s++)
                bhr[kt][g][s] = __ldg(&Bhi2g[((kt * 8 + w) * 6 + g * 2 + s) * 32 + lane]);

    for (int i = tid; i < 4 * HBUF; i += 256) hbase[i] = 0u;

    float bRr[2][2], bRz[2][2], biN[2][2], bhN[2][2];
#pragma unroll
    for (int s = 0; s < 2; s++)
#pragma unroll
        for (int jj = 0; jj < 2; jj++) {
            int c = w * 16 + s * 8 + 2 * qc + jj;
            bRr[s][jj] = __ldg(&bih[c]) + __ldg(&bhh[c]);
            bRz[s][jj] = __ldg(&bih[128 + c]) + __ldg(&bhh[128 + c]);
            biN[s][jj] = __ldg(&bih[256 + c]);
            bhN[s][jj] = __ldg(&bhh[256 + c]);
        }
    __syncthreads();

    const uint2* WihHi2 = (const uint2*)g_WihHi;
    int cur = 0;

    for (int t = 0; t < TT; t++) {
        uint32_t* h_hi_w = hbase + cur * (2 * HBUF);
        uint32_t* h_lo_w = h_hi_w + HBUF;
        uint32_t* n_hi_w = hbase + (cur ^ 1) * (2 * HBUF);
        uint32_t* n_lo_w = n_hi_w + HBUF;

        uint32_t xh[2][4], xl[2][4];
#pragma unroll
        for (int m = 0; m < 2; m++) {
            const float* base = feat + (size_t)(node0 + m * 16) * (TT * FF) + t * FF;
            float2 v[4];
            v[0] = __ldg((const float2*)(base + (size_t)qr * (TT * FF) + 2 * qc));
            v[1] = __ldg((const float2*)(base + (size_t)(qr + 8) * (TT * FF) + 2 * qc));
            v[2] = __ldg((const float2*)(base + (size_t)qr * (TT * FF) + 2 * qc + 8));
            v[3] = __ldg((const float2*)(base + (size_t)(qr + 8) * (TT * FF) + 2 * qc + 8));
#pragma unroll
            for (int j = 0; j < 4; j++) {
                __nv_bfloat162 hv; hv.x = __float2bfloat16(v[j].x); hv.y = __float2bfloat16(v[j].y);
                xh[m][j] = *(uint32_t*)&hv;
                __nv_bfloat162 lv;
                lv.x = __float2bfloat16(v[j].x - __bfloat162float(hv.x));
                lv.y = __float2bfloat16(v[j].y - __bfloat162float(hv.y));
                xl[m][j] = *(uint32_t*)&lv;
            }
        }

        float d[2][3][2][4];
        float dx[2][2][4];
#pragma unroll
        for (int m = 0; m < 2; m++) {
#pragma unroll
            for (int g = 0; g < 3; g++)
#pragma unroll
                for (int s = 0; s < 2; s++)
#pragma unroll
                    for (int j = 0; j < 4; j++) d[m][g][s][j] = 0.f;
#pragma unroll
            for (int s = 0; s < 2; s++)
#pragma unroll
                for (int j = 0; j < 4; j++) dx[m][s][j] = 0.f;
        }

        // ---- x @ Wih^T (k=16) ----
#pragma unroll
        for (int s = 0; s < 2; s++) {
            const uint32_t* p = &g_WihLo[((w * 2 + s) * 32 + lane) * 8];
            uint4 wlA = __ldg((const uint4*)p);
            uint2 wlB = __ldg((const uint2*)(p + 4));
            uint32_t wlw[6] = {wlA.x, wlA.y, wlA.z, wlA.w, wlB.x, wlB.y};
#pragma unroll
            for (int g = 0; g < 3; g++) {
                uint2 bh = __ldg(&WihHi2[(w * 6 + g * 2 + s) * 32 + lane]);
#pragma unroll
                for (int m = 0; m < 2; m++) {
                    float* D = (g == 2) ? dx[m][s] : d[m][g][s];
                    mma_bf16(D, xh[m], bh.x, bh.y);
                    mma_bf16(D, xl[m], bh.x, bh.y);
                    mma_bf16(D, xh[m], wlw[g * 2], wlw[g * 2 + 1]);
                }
            }
        }

        // ---- h @ Whh^T (bf16, B-hi from registers, lo streamed) ----
        if (t) {
#pragma unroll
            for (int kt = 0; kt < 8; kt++) {
                uint32_t ah[2][4], al[2][4];
#pragma unroll
                for (int m = 0; m < 2; m++) {
                    int r0 = (m * 16 + qr) * 68 + kt * 8 + qc;
                    ah[m][0] = h_hi_w[r0];
                    ah[m][1] = h_hi_w[r0 + 8 * 68];
                    ah[m][2] = h_hi_w[r0 + 4];
                    ah[m][3] = h_hi_w[r0 + 8 * 68 + 4];
                    al[m][0] = h_lo_w[r0];
                    al[m][1] = h_lo_w[r0 + 8 * 68];
                    al[m][2] = h_lo_w[r0 + 4];
                    al[m][3] = h_lo_w[r0 + 8 * 68 + 4];
                }
#pragma unroll
                for (int s = 0; s < 2; s++) {
                    const uint32_t* p = &g_Blo[(((kt * 8 + w) * 2 + s) * 32 + lane) * 8];
                    uint4 lA = __ldg((const uint4*)p);
                    uint2 lB = __ldg((const uint2*)(p + 4));
                    uint32_t lw[6] = {lA.x, lA.y, lA.z, lA.w, lB.x, lB.y};
#pragma unroll
                    for (int g = 0; g < 3; g++) {
                        uint2 bh = bhr[kt][g][s];
#pragma unroll
                        for (int m = 0; m < 2; m++) {
                            mma_bf16(d[m][g][s], ah[m], bh.x, bh.y);
                            mma_bf16(d[m][g][s], al[m], bh.x, bh.y);
                            mma_bf16(d[m][g][s], ah[m], lw[g * 2], lw[g * 2 + 1]);
                        }
                    }
                }
            }
        }

        // ---- gate math: read h[cur], write h[nxt], single barrier ----
#pragma unroll
        for (int m = 0; m < 2; m++)
#pragma unroll
            for (int s = 0; s < 2; s++)
#pragma unroll
                for (int rg = 0; rg < 2; rg++) {
                    int row = m * 16 + qr + rg * 8;
                    int wi = row * 68 + w * 8 + s * 4 + qc;
                    float2 hhf = __bfloat1622float2(*(__nv_bfloat162*)&h_hi_w[wi]);
                    float2 hlf = __bfloat1622float2(*(__nv_bfloat162*)&h_lo_w[wi]);
                    float hn[2];
#pragma unroll
                    for (int jj = 0; jj < 2; jj++) {
                        float hold = jj ? (hhf.y + hlf.y) : (hhf.x + hlf.x);
                        int di = rg * 2 + jj;
                        float rr = sigmoid_fast(d[m][0][s][di] + bRr[s][jj]);
                        float zz = sigmoid_fast(d[m][1][s][di] + bRz[s][jj]);
                        float nv = tanh_fast(dx[m][s][di] + biN[s][jj] +
                                             rr * (d[m][2][s][di] + bhN[s][jj]));
                        hn[jj] = (1.f - zz) * nv + zz * hold;
                    }
                    __nv_bfloat162 hv; hv.x = __float2bfloat16(hn[0]); hv.y = __float2bfloat16(hn[1]);
                    __nv_bfloat162 lv;
                    lv.x = __float2bfloat16(hn[0] - __bfloat162float(hv.x));
                    lv.y = __float2bfloat16(hn[1] - __bfloat162float(hv.y));
                    n_hi_w[wi] = *(uint32_t*)&hv;
                    n_lo_w[wi] = *(uint32_t*)&lv;
                }
        __syncthreads();
        cur ^= 1;
    }

    const __nv_bfloat16* h_hi = (const __nv_bfloat16*)(hbase + cur * (2 * HBUF));
    const __nv_bfloat16* h_lo = h_hi + 2 * HBUF;
    for (int i = tid; i < 32 * HH; i += 256) {
        int row = i >> 7, col = i & 127;
        g_support[(size_t)(node0 + row) * HH + col] =
            __bfloat162float(h_hi[row * 136 + col]) +
            __bfloat162float(h_lo[row * 136 + col]);
    }
}

// ---------------- kernel 3: bf16 GEMM C = A @ B (+b1+b2) [+f1/f2 epilogue] --
struct GemmJob {
    const float* A; const float* B; const float* b1; const float* b2; float* C;
    const float* u; const float* v; float* f1; float* f2;
};
struct GemmJobs { GemmJob j[5]; };

#define GEMM_SMEM (4 * 128 * 136 * 2)   // 139264 B

__global__ void __launch_bounds__(256) k_gemm(GemmJobs jobs) {
    GemmJob job = jobs.j[blockIdx.y];
    extern __shared__ char smc[];
    uint16_t* As_hi = (uint16_t*)smc;
    uint16_t* As_lo = As_hi + 128 * 136;
    uint16_t* Bs_hi = As_lo + 128 * 136;
    uint16_t* Bs_lo = Bs_hi + 128 * 136;
    int tid = threadIdx.x;
    int node0 = blockIdx.x * 128;

    for (int idx = tid; idx < 128 * 128; idx += 256) {
        int r = idx >> 7, c = idx & 127;
        float a = job.A[(size_t)(node0 + r) * HH + c];
        __nv_bfloat16 ah = __float2bfloat16(a);
        As_hi[r * 136 + c] = __bfloat16_as_ushort(ah);
        As_lo[r * 136 + c] =
            __bfloat16_as_ushort(__float2bfloat16(a - __bfloat162float(ah)));
        float b = job.B[idx];
        __nv_bfloat16 bh = __float2bfloat16(b);
        Bs_hi[c * 136 + r] = __bfloat16_as_ushort(bh);
        Bs_lo[c * 136 + r] =
            __bfloat16_as_ushort(__float2bfloat16(b - __bfloat162float(bh)));
    }
    __syncthreads();

    int w = tid >> 5, lane = tid & 31;
    int qr = lane >> 2, qc = lane & 3;
    int r0 = w * 16;
    const uint32_t* Aw_hi = (const uint32_t*)As_hi;
    const uint32_t* Aw_lo = (const uint32_t*)As_lo;
    const uint32_t* Bw_hi = (const uint32_t*)Bs_hi;
    const uint32_t* Bw_lo = (const uint32_t*)Bs_lo;

    float acc[16][4];
#pragma unroll
    for (int ct = 0; ct < 16; ct++)
#pragma unroll
        for (int j = 0; j < 4; j++) acc[ct][j] = 0.f;

#pragma unroll 1
    for (int kt = 0; kt < 8; kt++) {
        int kc = kt * 8 + qc;
        uint32_t ah[4], al[4];
        ah[0] = Aw_hi[(r0 + qr) * 68 + kc];
        ah[1] = Aw_hi[(r0 + qr + 8) * 68 + kc];
        ah[2] = Aw_hi[(r0 + qr) * 68 + kc + 4];
        ah[3] = Aw_hi[(r0 + qr + 8) * 68 + kc + 4];
        al[0] = Aw_lo[(r0 + qr) * 68 + kc];
        al[1] = Aw_lo[(r0 + qr + 8) * 68 + kc];
        al[2] = Aw_lo[(r0 + qr) * 68 + kc + 4];
        al[3] = Aw_lo[(r0 + qr + 8) * 68 + kc + 4];
#pragma unroll
        for (int cg = 0; cg < 4; cg++) {
            uint32_t bh0[4], bh1[4], bl0[4], bl1[4];
#pragma unroll
            for (int j = 0; j < 4; j++) {
                int n0 = (cg * 4 + j) * 8;
                bh0[j] = Bw_hi[(n0 + qr) * 68 + kc];
                bh1[j] = Bw_hi[(n0 + qr) * 68 + kc + 4];
                bl0[j] = Bw_lo[(n0 + qr) * 68 + kc];
                bl1[j] = Bw_lo[(n0 + qr) * 68 + kc + 4];
            }
#pragma unroll
            for (int j = 0; j < 4; j++)
                mma_bf16(acc[cg * 4 + j], ah, bh0[j], bh1[j]);
#pragma unroll
            for (int j = 0; j < 4; j++)
                mma_bf16(acc[cg * 4 + j], al, bh0[j], bh1[j]);
#pragma unroll
            for (int j = 0; j < 4; j++)
                mma_bf16(acc[cg * 4 + j], ah, bl0[j], bl1[j]);
        }
    }

#pragma unroll
    for (int ct = 0; ct < 16; ct++) {
        int c0 = ct * 8 + 2 * qc;
        float b0 = 0.f, b1v = 0.f;
        if (job.b1) { b0 += __ldg(&job.b1[c0]); b1v += __ldg(&job.b1[c0 + 1]); }
        if (job.b2) { b0 += __ldg(&job.b2[c0]); b1v += __ldg(&job.b2[c0 + 1]); }
        acc[ct][0] += b0; acc[ct][1] += b1v;
        acc[ct][2] += b0; acc[ct][3] += b1v;
        int r = node0 + r0 + qr;
        *(float2*)&job.C[(size_t)r * HH + c0] = make_float2(acc[ct][0], acc[ct][1]);
        *(float2*)&job.C[(size_t)(r + 8) * HH + c0] = make_float2(acc[ct][2], acc[ct][3]);
    }

    // ---- fused f1/f2 epilogue (attention logits per head) ----
    if (job.u) {
        float f1p[2][4], f2p[2][4];
#pragma unroll
        for (int rh = 0; rh < 2; rh++)
#pragma unroll
            for (int h = 0; h < 4; h++) { f1p[rh][h] = 0.f; f2p[rh][h] = 0.f; }
#pragma unroll
        for (int ct = 0; ct < 16; ct++) {
            int h = ct >> 2;
            int c0 = ct * 8 + 2 * qc;
            float u0 = __ldg(&job.u[c0]),     u1 = __ldg(&job.u[c0 + 1]);
            float v0 = __ldg(&job.v[c0]),     v1 = __ldg(&job.v[c0 + 1]);
            f1p[0][h] += acc[ct][0] * u0 + acc[ct][1] * u1;
            f2p[0][h] += acc[ct][0] * v0 + acc[ct][1] * v1;
            f1p[1][h] += acc[ct][2] * u0 + acc[ct][3] * u1;
            f2p[1][h] += acc[ct][2] * v0 + acc[ct][3] * v1;
        }
#pragma unroll
        for (int rh = 0; rh < 2; rh++)
#pragma unroll
            for (int h = 0; h < 4; h++) {
                f1p[rh][h] += __shfl_xor_sync(0xffffffffu, f1p[rh][h], 1);
                f1p[rh][h] += __shfl_xor_sync(0xffffffffu, f1p[rh][h], 2);
                f2p[rh][h] += __shfl_xor_sync(0xffffffffu, f2p[rh][h], 1);
                f2p[rh][h] += __shfl_xor_sync(0xffffffffu, f2p[rh][h], 2);
            }
        if (qc == 0) {
#pragma unroll
            for (int rh = 0; rh < 2; rh++) {
                int r = node0 + r0 + qr + rh * 8;
#pragma unroll
                for (int h = 0; h < 4; h++) {
                    job.f1[h * NN + r] = f1p[rh][h];
                    job.f2[h * NN + r] = f2p[rh][h];
                }
            }
        }
    }
}

// ---------------- kernel 5: GAT aggregation, precomputed weights ------------
__global__ void __launch_bounds__(128) k_gat(const float* __restrict__ adjP,
                                             const float* __restrict__ adjN) {
    __shared__ __align__(128) float tile[NN];        // 16 KB; reused as s_jw
    __shared__ __align__(8) uint64_t mbar;
    __shared__ int s_cnt;
    __shared__ int s_list[512];
    __shared__ float s_a[512];
    const float* adj; const float* sup; const float* f1; const float* f2;
    const float* resid; float* outp;
    if (blockIdx.y == 0) { adj = adjP; sup = g_supP; f1 = g_f1P; f2 = g_f2P; resid = g_residP; outp = g_gatP; }
    else                 { adj = adjN; sup = g_supN; f1 = g_f1N; f2 = g_f2N; resid = g_residN; outp = g_gatN; }
    int i = blockIdx.x, tid = threadIdx.x;
    int h = tid >> 5, lane = tid & 31;

    uint32_t tile_a = (uint32_t)__cvta_generic_to_shared(tile);
    uint32_t mbar_a = (uint32_t)__cvta_generic_to_shared(&mbar);
    if (tid == 0) {
        s_cnt = 0;
        asm volatile("mbarrier.init.shared.b64 [%0], 1;" :: "r"(mbar_a) : "memory");
        asm volatile("fence.proxy.async.shared::cta;" ::: "memory");
        asm volatile("mbarrier.arrive.expect_tx.shared.b64 _, [%0], %1;"
                     :: "r"(mbar_a), "r"((uint32_t)(NN * 4)) : "memory");
        asm volatile("cp.async.bulk.shared::cta.global.mbarrier::complete_tx::bytes "
                     "[%0], [%1], %2, [%3];"
                     :: "r"(tile_a), "l"(adj + (size_t)i * NN),
                        "r"((uint32_t)(NN * 4)), "r"(mbar_a) : "memory");
    }
    __syncthreads();
    {
        uint32_t done;
        do {
            asm volatile("{\n\t.reg .pred p;\n\t"
                         "mbarrier.try_wait.parity.acquire.cta.shared::cta.b64 p, [%1], %2;\n\t"
                         "selp.b32 %0, 1, 0, p;\n\t}"
                         : "=r"(done) : "r"(mbar_a), "r"(0u) : "memory");
        } while (!done);
    }

    // scan from shared
    const float4* t4 = (const float4*)tile;
    for (int j4 = tid; j4 < NN / 4; j4 += 128) {
        float4 a = t4[j4];
        if (a.x != 0.f) { int p = atomicAdd(&s_cnt, 1); s_list[p] = j4 * 4 + 0; s_a[p] = a.x; }
        if (a.y != 0.f) { int p = atomicAdd(&s_cnt, 1); s_list[p] = j4 * 4 + 1; s_a[p] = a.y; }
        if (a.z != 0.f) { int p = atomicAdd(&s_cnt, 1); s_list[p] = j4 * 4 + 2; s_a[p] = a.z; }
        if (a.w != 0.f) { int p = atomicAdd(&s_cnt, 1); s_list[p] = j4 * 4 + 3; s_a[p] = a.w; }
    }
    __syncthreads();      // tile reads done; safe to overlay s_jw on it
    int cnt = s_cnt;

    // precompute (byte-offset, weight) per head, cooperative across lanes
    float2* s_jw = (float2*)tile;                   // [4][512] = 16 KB
    float f2i = f2[h * NN + i];
    float den = 0.f;
    for (int t = lane; t < cnt; t += 32) {
        int j = s_list[t];
        float wv = __ldg(&f1[h * NN + j]) + f2i;
        wv = ((wv > 0.f) ? wv : 0.2f * wv) * s_a[t];
        den += wv;
        s_jw[h * 512 + t] = make_float2(__int_as_float(j * (HH * 4)), wv);
    }
    den = warpsum_bfly(den);
    __syncwarp();

    // gather: minimal loop (LDS.64 + LDG + FFMA)
    const char* supb = (const char*)(sup + tid);
    const float2* jw = &s_jw[h * 512];
    float num = 0.f;
    for (int t = 0; t < cnt; t++) {
        float2 p = jw[t];
        num += p.y * __ldg((const float*)(supb + __float_as_int(p.x)));
    }
    float d = (den == 0.f) ? 1.f : den;
    outp[(size_t)i * HH + tid] = num / d + resid[(size_t)i * HH + tid];
}

// ---------------- kernel 7: semantic attention, warp-per-node ----------------
__global__ void __launch_bounds__(256) k_sem(const float* __restrict__ W1,
                                             const float* __restrict__ b1,
                                             const float* __restrict__ W2) {
    __shared__ float W1s[128 * 65];
    __shared__ float W2s[SEMD], b1s[SEMD];
    __shared__ float semb[8][3][128];
    int tid = threadIdx.x;
    for (int i = tid; i < 128 * 64; i += 256) {
        int k = i >> 6, s = i & 63;
        W1s[k * 65 + s] = W1[i];
    }
    if (tid < SEMD) { W2s[tid] = W2[tid]; b1s[tid] = b1[tid]; }
    __syncthreads();

    int w = tid >> 5, lane = tid & 31;
    float csum[4] = {0.f, 0.f, 0.f, 0.f};
    int nbase = (blockIdx.x * 8 + w) * 8;

    for (int i = 0; i < 8; i++) {
        int n = nbase + i;
        float4 ev[3];
        ev[0] = *(const float4*)&g_selfE[(size_t)n * HH + lane * 4];
        ev[1] = *(const float4*)&g_posE[(size_t)n * HH + lane * 4];
        ev[2] = *(const float4*)&g_negE[(size_t)n * HH + lane * 4];
        __syncwarp();
        *(float4*)&semb[w][0][lane * 4] = ev[0];
        *(float4*)&semb[w][1][lane * 4] = ev[1];
        *(float4*)&semb[w][2][lane * 4] = ev[2];
        __syncwarp();

        float acc[3][2];
#pragma unroll
        for (int e = 0; e < 3; e++) { acc[e][0] = b1s[lane]; acc[e][1] = b1s[lane + 32]; }
#pragma unroll 4
        for (int k = 0; k < HH; k++) {
            float w1a = W1s[k * 65 + lane];
            float w1b = W1s[k * 65 + lane + 32];
            float x0 = semb[w][0][k], x1 = semb[w][1][k], x2 = semb[w][2][k];
            acc[0][0] += x0 * w1a; acc[0][1] += x0 * w1b;
            acc[1][0] += x1 * w1a; acc[1][1] += x1 * w1b;
            acc[2][0] += x2 * w1a; acc[2][1] += x2 * w1b;
        }
        float wv[3];
#pragma unroll
        for (int e = 0; e < 3; e++) {
            float tsum = tanh_fast(acc[e][0]) * W2s[lane] +
                         tanh_fast(acc[e][1]) * W2s[lane + 32];
            wv[e] = warpsum_bfly(tsum);
        }
        float m = fmaxf(wv[0], fmaxf(wv[1], wv[2]));
        float e0 = __expf(wv[0] - m), e1 = __expf(wv[1] - m), e2 = __expf(wv[2] - m);
        float inv = __fdividef(1.f, e0 + e1 + e2);
        float be0 = e0 * inv, be1 = e1 * inv, be2 = e2 * inv;
        float4 f;
        f.x = be0 * ev[0].x + be1 * ev[1].x + be2 * ev[2].x;
        f.y = be0 * ev[0].y + be1 * ev[1].y + be2 * ev[2].y;
        f.z = be0 * ev[0].z + be1 * ev[1].z + be2 * ev[2].z;
        f.w = be0 * ev[0].w + be1 * ev[1].w + be2 * ev[2].w;
        *(float4*)&g_fused[(size_t)n * HH + lane * 4] = f;
        csum[0] += f.x; csum[1] += f.y; csum[2] += f.z; csum[3] += f.w;
    }
    atomicAdd(&g_colsum[lane * 4 + 0], csum[0]);
    atomicAdd(&g_colsum[lane * 4 + 1], csum[1]);
    atomicAdd(&g_colsum[lane * 4 + 2], csum[2]);
    atomicAdd(&g_colsum[lane * 4 + 3], csum[3]);
}

// ---------------- kernel 8: pairnorm + predictor -----------------------------
__global__ void __launch_bounds__(256) k_pred(const float* __restrict__ W1,
                                              const float* __restrict__ b1,
                                              const float* __restrict__ W2,
                                              const float* __restrict__ b2,
                                              float* __restrict__ out) {
    __shared__ float W1s[HH * PHD];
    __shared__ float xns[8][HH];
    int tid = threadIdx.x;
    for (int i = tid; i < HH * PHD; i += 256) W1s[i] = W1[i];
    int w = tid >> 5, lane = tid & 31;
    int n = blockIdx.x * 8 + w;
    float xv[4]; float ss = 0.f;
    const float invN = 1.f / (float)NN;
#pragma unroll
    for (int j = 0; j < 4; j++) {
        int d = lane + j * 32;
        float x = g_fused[(size_t)n * HH + d] - g_colsum[d] * invN;
        xv[j] = x; ss += x * x;
    }
    ss = warpsum(ss);
    ss = __shfl_sync(0xffffffffu, ss, 0);
    float rinv = rsqrtf(1e-6f + ss);
#pragma unroll
    for (int j = 0; j < 4; j++) xns[w][lane + j * 32] = xv[j] * rinv;
    __syncthreads();

    float acc = b1[lane];
#pragma unroll 4
    for (int k = 0; k < HH; k++) acc += xns[w][k] * W1s[k * PHD + lane];
    float hgt = acc > 0.f ? acc : 0.f;
    float o = warpsum(hgt * W2[lane]);
    if (lane == 0) out[n] = sigmoid_fast(o + b2[0]);
}

// ---------------- launch -----------------------------------------------------
extern "C" void kernel_launch(void* const* d_in, const int* in_sizes, int n_in,
                              void* d_out, int out_size) {
    const float* features = (const float*)d_in[0];
    const float* pos_adj  = (const float*)d_in[1];
    const float* neg_adj  = (const float*)d_in[2];
    const float* gru_Wih  = (const float*)d_in[3];
    const float* gru_Whh  = (const float*)d_in[4];
    const float* gru_bih  = (const float*)d_in[5];
    const float* gru_bhh  = (const float*)d_in[6];
    const float* pos_W    = (const float*)d_in[7];
    const float* pos_u    = (const float*)d_in[8];
    const float* pos_v    = (const float*)d_in[9];
    const float* pos_b    = (const float*)d_in[10];
    const float* pos_pW   = (const float*)d_in[11];
    const float* pos_pb   = (const float*)d_in[12];
    const float* neg_W    = (const float*)d_in[13];
    const float* neg_u    = (const float*)d_in[14];
    const float* neg_v    = (const float*)d_in[15];
    const float* neg_b    = (const float*)d_in[16];
    const float* neg_pW   = (const float*)d_in[17];
    const float* neg_pb   = (const float*)d_in[18];
    const float* self_W   = (const float*)d_in[19];
    const float* self_b   = (const float*)d_in[20];
    const float* mpos_W   = (const float*)d_in[21];
    const float* mpos_b   = (const float*)d_in[22];
    const float* mneg_W   = (const float*)d_in[23];
    const float* mneg_b   = (const float*)d_in[24];
    const float* sem_W1   = (const float*)d_in[25];
    const float* sem_b1   = (const float*)d_in[26];
    const float* sem_W2   = (const float*)d_in[27];
    const float* pred_W1  = (const float*)d_in[28];
    const float* pred_b1  = (const float*)d_in[29];
    const float* pred_W2  = (const float*)d_in[30];
    const float* pred_b2  = (const float*)d_in[31];
    float* out = (float*)d_out;

    static bool attr_done = false;
    if (!attr_done) {
        cudaFuncSetAttribute(k_gemm, cudaFuncAttributeMaxDynamicSharedMemorySize, GEMM_SMEM);
        attr_done = true;
    }

    float *p_support, *p_gatP, *p_gatN, *p_supP, *p_supN;
    float *p_residP, *p_residN, *p_selfE, *p_posE, *p_negE;
    float *p_f1P, *p_f2P, *p_f1N, *p_f2N;
    cudaGetSymbolAddress((void**)&p_support, g_support);
    cudaGetSymbolAddress((void**)&p_supP, g_supP);
    cudaGetSymbolAddress((void**)&p_supN, g_supN);
    cudaGetSymbolAddress((void**)&p_residP, g_residP);
    cudaGetSymbolAddress((void**)&p_residN, g_residN);
    cudaGetSymbolAddress((void**)&p_selfE, g_selfE);
    cudaGetSymbolAddress((void**)&p_gatP, g_gatP);
    cudaGetSymbolAddress((void**)&p_gatN, g_gatN);
    cudaGetSymbolAddress((void**)&p_posE, g_posE);
    cudaGetSymbolAddress((void**)&p_negE, g_negE);
    cudaGetSymbolAddress((void**)&p_f1P, g_f1P);
    cudaGetSymbolAddress((void**)&p_f2P, g_f2P);
    cudaGetSymbolAddress((void**)&p_f1N, g_f1N);
    cudaGetSymbolAddress((void**)&p_f2N, g_f2N);

    k_prep_all<<<54, 256>>>(gru_Whh, gru_Wih);                      // 1
    k_gru<<<NN / 32, 256>>>(features, gru_bih, gru_bhh);            // 2
    {
        GemmJobs jb;
        jb.j[0] = { p_support, pos_W,  nullptr, nullptr, p_supP, pos_u, pos_v, p_f1P, p_f2P };
        jb.j[1] = { p_support, neg_W,  nullptr, nullptr, p_supN, neg_u, neg_v, p_f1N, p_f2N };
        jb.j[2] = { p_support, pos_pW, pos_b,   pos_pb,  p_residP, nullptr, nullptr, nullptr, nullptr };
        jb.j[3] = { p_support, neg_pW, neg_b,   neg_pb,  p_residN, nullptr, nullptr, nullptr, nullptr };
        jb.j[4] = { p_support, self_W, self_b,  nullptr, p_selfE, nullptr, nullptr, nullptr, nullptr };
        dim3 grid(NN / 128, 5);
        k_gemm<<<grid, 256, GEMM_SMEM>>>(jb);                       // 3
    }
    {
        dim3 grid(NN, 2);
        k_gat<<<grid, 128>>>(pos_adj, neg_adj);                     // 4
    }
    {
        GemmJobs jb;
        jb.j[0] = { p_gatP, mpos_W, mpos_b, nullptr, p_posE, nullptr, nullptr, nullptr, nullptr };
        jb.j[1] = { p_gatN, mneg_W, mneg_b, nullptr, p_negE, nullptr, nullptr, nullptr, nullptr };
        jb.j[2] = jb.j[0]; jb.j[3] = jb.j[0]; jb.j[4] = jb.j[0];
        dim3 grid(NN / 128, 2);
        k_gemm<<<grid, 256, GEMM_SMEM>>>(jb);                       // 5
    }
    k_sem<<<NN / 64, 256>>>(sem_W1, sem_b1, sem_W2);                // 6
    k_pred<<<NN / 8, 256>>>(pred_W1, pred_b1, pred_W2, pred_b2, out); // 7
}